// round 1
// baseline (speedup 1.0000x reference)
#include <cuda_runtime.h>
#include <math.h>
#include <stdint.h>

// ---------------------------------------------------------------------------
// Problem constants
//   B=8, C=512, H=W=128, WS=8, NH=8, hd=64, L=64 tokens/window,
//   N=256 windows/batch, TOKS = 8*256*64 = 131072 tokens
// ---------------------------------------------------------------------------
#define TOKS 131072
#define CDIM 512

// Scratch (device globals — no cudaMalloc allowed)
__device__ float g_t  [(size_t)TOKS * 512];    // partitioned tokens / residual stream
__device__ float g_xn [(size_t)TOKS * 512];    // layernorm output (reused for LN2)
__device__ float g_qkv[(size_t)TOKS * 1536];   // qkv projection
__device__ float g_o  [(size_t)TOKS * 512];    // attention output
__device__ float g_h  [(size_t)TOKS * 2048];   // MLP hidden

// ---------------------------------------------------------------------------
// Kernel 1: window partition + LayerNorm1.
// token -> (b, n, l); x offset = ((b*512+c)*128 + h)*128 + w
// ---------------------------------------------------------------------------
__global__ void __launch_bounds__(128) ln1_part_k(
    const float* __restrict__ x, const float* __restrict__ gamma,
    const float* __restrict__ beta, float* __restrict__ t, float* __restrict__ xn)
{
    int tok = blockIdx.x;
    int tid = threadIdx.x;
    int b = tok >> 14;
    int n = (tok >> 6) & 255;
    int l = tok & 63;
    int h = ((n >> 4) << 3) | (l >> 3);
    int w = ((n & 15) << 3) | (l & 7);
    size_t base = ((size_t)b * 512) * 16384 + (size_t)(h << 7) + w;

    float v[4];
    float s = 0.f, s2 = 0.f;
#pragma unroll
    for (int k = 0; k < 4; k++) {
        int c = tid + (k << 7);
        v[k] = x[base + ((size_t)c << 14)];
        s += v[k]; s2 += v[k] * v[k];
    }
#pragma unroll
    for (int off = 16; off; off >>= 1) {
        s  += __shfl_xor_sync(0xffffffffu, s,  off);
        s2 += __shfl_xor_sync(0xffffffffu, s2, off);
    }
    __shared__ float sh[8];
    int wid = tid >> 5, lane = tid & 31;
    if (lane == 0) { sh[wid] = s; sh[4 + wid] = s2; }
    __syncthreads();
    s  = sh[0] + sh[1] + sh[2] + sh[3];
    s2 = sh[4] + sh[5] + sh[6] + sh[7];
    float mu  = s  * (1.f / 512.f);
    float var = s2 * (1.f / 512.f) - mu * mu;
    float rs  = rsqrtf(var + 1e-5f);

    size_t tb = (size_t)tok * 512;
#pragma unroll
    for (int k = 0; k < 4; k++) {
        int c = tid + (k << 7);
        t [tb + c] = v[k];
        xn[tb + c] = (v[k] - mu) * rs * gamma[c] + beta[c];
    }
}

// ---------------------------------------------------------------------------
// Kernel: LayerNorm2 (contiguous source)
// ---------------------------------------------------------------------------
__global__ void __launch_bounds__(128) ln2_k(
    const float* __restrict__ src, const float* __restrict__ gamma,
    const float* __restrict__ beta, float* __restrict__ xn)
{
    int tok = blockIdx.x;
    int tid = threadIdx.x;
    size_t tb = (size_t)tok * 512;

    float v[4];
    float s = 0.f, s2 = 0.f;
#pragma unroll
    for (int k = 0; k < 4; k++) {
        int c = tid + (k << 7);
        v[k] = src[tb + c];
        s += v[k]; s2 += v[k] * v[k];
    }
#pragma unroll
    for (int off = 16; off; off >>= 1) {
        s  += __shfl_xor_sync(0xffffffffu, s,  off);
        s2 += __shfl_xor_sync(0xffffffffu, s2, off);
    }
    __shared__ float sh[8];
    int wid = tid >> 5, lane = tid & 31;
    if (lane == 0) { sh[wid] = s; sh[4 + wid] = s2; }
    __syncthreads();
    s  = sh[0] + sh[1] + sh[2] + sh[3];
    s2 = sh[4] + sh[5] + sh[6] + sh[7];
    float mu  = s  * (1.f / 512.f);
    float var = s2 * (1.f / 512.f) - mu * mu;
    float rs  = rsqrtf(var + 1e-5f);
#pragma unroll
    for (int k = 0; k < 4; k++) {
        int c = tid + (k << 7);
        xn[tb + c] = (v[k] - mu) * rs * gamma[c] + beta[c];
    }
}

// ---------------------------------------------------------------------------
// Attention: one CTA per (window, head). L=64 tokens, hd=64.
// thread = (row = tid>>2, quarter q4 = tid&3). Scores & softmax in registers,
// 4-lane shuffle reduction. K/V staged in SMEM [64][68] (pad -> conflict-light).
// scores = (q . k) / 4096
// ---------------------------------------------------------------------------
__global__ void __launch_bounds__(256) attn_k(
    const float* __restrict__ qkv, float* __restrict__ o)
{
    __shared__ float ks[64][68];
    __shared__ float vs[64][68];

    int tid  = threadIdx.x;
    int win  = blockIdx.x >> 3;
    int head = blockIdx.x & 7;
    const float* base = qkv + (size_t)win * 64 * 1536 + head * 64;

    int row = tid >> 2;
    int q4  = tid & 3;
    int e0  = q4 << 4;

    // stage K, V
    {
        const float* kp = base + 512  + (size_t)row * 1536 + e0;
        const float* vp = base + 1024 + (size_t)row * 1536 + e0;
#pragma unroll
        for (int s = 0; s < 4; s++) {
            *(float4*)&ks[row][e0 + s * 4] = *(const float4*)(kp + s * 4);
            *(float4*)&vs[row][e0 + s * 4] = *(const float4*)(vp + s * 4);
        }
    }
    // q quarter in registers, pre-scaled by 1/4096
    float qreg[16];
    {
        const float scl = 1.f / 4096.f;
        const float* qp = base + (size_t)row * 1536 + e0;
#pragma unroll
        for (int s = 0; s < 4; s++) {
            float4 q = *(const float4*)(qp + s * 4);
            qreg[s*4+0] = q.x * scl; qreg[s*4+1] = q.y * scl;
            qreg[s*4+2] = q.z * scl; qreg[s*4+3] = q.w * scl;
        }
    }
    __syncthreads();

    // partial scores over this thread's e-quarter, all 64 keys
    float p[64];
#pragma unroll
    for (int m = 0; m < 64; m++) {
        float acc = 0.f;
#pragma unroll
        for (int s = 0; s < 4; s++) {
            float4 kv = *(float4*)&ks[m][e0 + s * 4];
            acc += qreg[s*4+0] * kv.x + qreg[s*4+1] * kv.y
                 + qreg[s*4+2] * kv.z + qreg[s*4+3] * kv.w;
        }
        p[m] = acc;
    }
    // reduce partials across the 4 lanes of this row
#pragma unroll
    for (int m = 0; m < 64; m++) {
        p[m] += __shfl_xor_sync(0xffffffffu, p[m], 1);
        p[m] += __shfl_xor_sync(0xffffffffu, p[m], 2);
    }
    // softmax (every lane holds the full row redundantly)
    float mx = -1e30f;
#pragma unroll
    for (int m = 0; m < 64; m++) mx = fmaxf(mx, p[m]);
    float sum = 0.f;
#pragma unroll
    for (int m = 0; m < 64; m++) { p[m] = expf(p[m] - mx); sum += p[m]; }
    float inv = 1.f / sum;

    // AV: this lane computes o[row][e0..e0+15]
    float oa[16];
#pragma unroll
    for (int e = 0; e < 16; e++) oa[e] = 0.f;
#pragma unroll
    for (int m = 0; m < 64; m++) {
        float a = p[m] * inv;
#pragma unroll
        for (int s = 0; s < 4; s++) {
            float4 vv = *(float4*)&vs[m][e0 + s * 4];
            oa[s*4+0] += a * vv.x; oa[s*4+1] += a * vv.y;
            oa[s*4+2] += a * vv.z; oa[s*4+3] += a * vv.w;
        }
    }
    float* op = o + (size_t)win * 64 * 512 + (size_t)row * 512 + head * 64 + e0;
#pragma unroll
    for (int s = 0; s < 4; s++)
        *(float4*)(op + s * 4) = make_float4(oa[s*4+0], oa[s*4+1], oa[s*4+2], oa[s*4+3]);
}

// ---------------------------------------------------------------------------
// SGEMM: C[M,N] = A[M,K] @ B[K,N] (+bias, + epilogue variants)
//   MODE 0: C = A@B + bias
//   MODE 1: C += A@B + bias                          (residual in place)
//   MODE 2: C = gelu_exact(A@B + bias)
//   MODE 3: out[window-unpartitioned x-layout] = Cres + A@B + bias
// BM=BN=128, BK=16, 256 threads, 8x8 per-thread tile.
// M,N multiples of 128; K multiple of 16. No bounds checks needed.
// ---------------------------------------------------------------------------
#define BM 128
#define BN 128
#define BK 16

__device__ __forceinline__ float gelu_exact(float v) {
    return 0.5f * v * (1.0f + erff(v * 0.70710678118654752440f));
}

template <int MODE>
__global__ void __launch_bounds__(256, 2) sgemm_k(
    const float* __restrict__ A, const float* __restrict__ B,
    const float* __restrict__ bias, float* __restrict__ C,
    float* __restrict__ out, int M, int N, int K)
{
    __shared__ float As[BK][BM];
    __shared__ float Bs[BK][BN];

    int tid  = threadIdx.x;
    int row0 = blockIdx.y * BM;
    int col0 = blockIdx.x * BN;

    int a_r = tid >> 2;              // 0..63
    int a_c = (tid & 3) << 2;        // 0,4,8,12
    int b_r = tid >> 5;              // 0..7
    int b_c = (tid & 31) << 2;       // 0..124

    const float* Ab = A + (size_t)row0 * K;
    const float* Bb = B + col0;

    int tx = tid & 15, ty = tid >> 4;
    float acc[8][8];
#pragma unroll
    for (int i = 0; i < 8; i++)
#pragma unroll
        for (int j = 0; j < 8; j++) acc[i][j] = 0.f;

    for (int k0 = 0; k0 < K; k0 += BK) {
#pragma unroll
        for (int s = 0; s < 2; s++) {
            float4 v = *(const float4*)(Ab + (size_t)(a_r + s * 64) * K + k0 + a_c);
            As[a_c + 0][a_r + s * 64] = v.x;
            As[a_c + 1][a_r + s * 64] = v.y;
            As[a_c + 2][a_r + s * 64] = v.z;
            As[a_c + 3][a_r + s * 64] = v.w;
        }
#pragma unroll
        for (int s = 0; s < 2; s++) {
            float4 v = *(const float4*)(Bb + (size_t)(k0 + b_r + s * 8) * N + b_c);
            *(float4*)&Bs[b_r + s * 8][b_c] = v;
        }
        __syncthreads();

        float ar[8], br[8];
#pragma unroll
        for (int kk = 0; kk < BK; kk++) {
            *(float4*)(ar)     = *(float4*)&As[kk][ty * 8];
            *(float4*)(ar + 4) = *(float4*)&As[kk][ty * 8 + 4];
            *(float4*)(br)     = *(float4*)&Bs[kk][tx * 8];
            *(float4*)(br + 4) = *(float4*)&Bs[kk][tx * 8 + 4];
#pragma unroll
            for (int i = 0; i < 8; i++)
#pragma unroll
                for (int j = 0; j < 8; j++) acc[i][j] += ar[i] * br[j];
        }
        __syncthreads();
    }

    // ---- epilogue ----
    float breg[8];
#pragma unroll
    for (int j = 0; j < 8; j++) breg[j] = bias[col0 + tx * 8 + j];

    if (MODE == 0 || MODE == 2) {
#pragma unroll
        for (int i = 0; i < 8; i++) {
            size_t idx = (size_t)(row0 + ty * 8 + i) * N + col0 + tx * 8;
            float v[8];
#pragma unroll
            for (int j = 0; j < 8; j++) {
                v[j] = acc[i][j] + breg[j];
                if (MODE == 2) v[j] = gelu_exact(v[j]);
            }
            *(float4*)&C[idx]     = make_float4(v[0], v[1], v[2], v[3]);
            *(float4*)&C[idx + 4] = make_float4(v[4], v[5], v[6], v[7]);
        }
    } else if (MODE == 1) {
#pragma unroll
        for (int i = 0; i < 8; i++) {
            size_t idx = (size_t)(row0 + ty * 8 + i) * N + col0 + tx * 8;
            float4 c0 = *(float4*)&C[idx];
            float4 c1 = *(float4*)&C[idx + 4];
            c0.x += acc[i][0] + breg[0]; c0.y += acc[i][1] + breg[1];
            c0.z += acc[i][2] + breg[2]; c0.w += acc[i][3] + breg[3];
            c1.x += acc[i][4] + breg[4]; c1.y += acc[i][5] + breg[5];
            c1.z += acc[i][6] + breg[6]; c1.w += acc[i][7] + breg[7];
            *(float4*)&C[idx]     = c0;
            *(float4*)&C[idx + 4] = c1;
        }
    } else { // MODE 3: final = t + A@B + bias, scattered to (B,C,H,W)
        int r0 = row0 + ty * 8;          // 8 consecutive tokens -> 8 consecutive w
        int b  = r0 >> 14;
        int n  = (r0 >> 6) & 255;
        int l0 = r0 & 63;                 // multiple of 8
        int hh = ((n >> 4) << 3) | (l0 >> 3);
        int w0 = (n & 15) << 3;
        size_t sbase = ((size_t)(b * 512) << 14) + (size_t)(hh << 7) + w0;
#pragma unroll
        for (int j = 0; j < 8; j++) {
            int col = col0 + tx * 8 + j;
            float v[8];
#pragma unroll
            for (int i = 0; i < 8; i++)
                v[i] = acc[i][j] + breg[j] + C[(size_t)(r0 + i) * N + col];
            float* op = out + sbase + ((size_t)col << 14);
            *(float4*)(op)     = make_float4(v[0], v[1], v[2], v[3]);
            *(float4*)(op + 4) = make_float4(v[4], v[5], v[6], v[7]);
        }
    }
}

// ---------------------------------------------------------------------------
// Launch sequence
// ---------------------------------------------------------------------------
extern "C" void kernel_launch(void* const* d_in, const int* in_sizes, int n_in,
                              void* d_out, int out_size)
{
    const float* x     = (const float*)d_in[0];
    const float* g1    = (const float*)d_in[1];
    const float* be1   = (const float*)d_in[2];
    const float* g2    = (const float*)d_in[3];
    const float* be2   = (const float*)d_in[4];
    const float* w_qkv = (const float*)d_in[5];
    const float* b_qkv = (const float*)d_in[6];
    const float* w_out = (const float*)d_in[7];
    const float* b_out = (const float*)d_in[8];
    const float* w1    = (const float*)d_in[9];
    const float* b1m   = (const float*)d_in[10];
    const float* w2    = (const float*)d_in[11];
    const float* b2m   = (const float*)d_in[12];
    float* out = (float*)d_out;

    float *t, *xn, *qkv, *o, *hbuf;
    cudaGetSymbolAddress((void**)&t,    g_t);
    cudaGetSymbolAddress((void**)&xn,   g_xn);
    cudaGetSymbolAddress((void**)&qkv,  g_qkv);
    cudaGetSymbolAddress((void**)&o,    g_o);
    cudaGetSymbolAddress((void**)&hbuf, g_h);

    // 1. window partition + LN1
    ln1_part_k<<<TOKS, 128>>>(x, g1, be1, t, xn);
    // 2. qkv = xn @ w_qkv + b_qkv
    sgemm_k<0><<<dim3(1536 / BN, TOKS / BM), 256>>>(xn, w_qkv, b_qkv, qkv, nullptr, TOKS, 1536, 512);
    // 3. windowed attention per (window, head)
    attn_k<<<(TOKS / 64) * 8, 256>>>(qkv, o);
    // 4. t += o @ w_out + b_out
    sgemm_k<1><<<dim3(512 / BN, TOKS / BM), 256>>>(o, w_out, b_out, t, nullptr, TOKS, 512, 512);
    // 5. LN2
    ln2_k<<<TOKS, 128>>>(t, g2, be2, xn);
    // 6. h = gelu(xn @ w1 + b1)
    sgemm_k<2><<<dim3(2048 / BN, TOKS / BM), 256>>>(xn, w1, b1m, hbuf, nullptr, TOKS, 2048, 512);
    // 7. out[x-layout] = t + h @ w2 + b2  (fused un-partition)
    sgemm_k<3><<<dim3(512 / BN, TOKS / BM), 256>>>(hbuf, w2, b2m, t, out, TOKS, 512, 2048);
}

// round 2
// speedup vs baseline: 1.8057x; 1.8057x over previous
#include <cuda_runtime.h>
#include <math.h>
#include <stdint.h>

// ---------------------------------------------------------------------------
// B=8, C=512, H=W=128, WS=8, NH=8, hd=64, L=64, N=256 windows/batch
// TOKS = 8*256*64 = 131072
// ---------------------------------------------------------------------------
#define TOKS 131072

// Scratch (device globals — no cudaMalloc allowed)
__device__ float g_t  [(size_t)TOKS * 512];
__device__ float g_xn [(size_t)TOKS * 512];
__device__ float g_qkv[(size_t)TOKS * 1536];
__device__ float g_o  [(size_t)TOKS * 512];
__device__ float g_h  [(size_t)TOKS * 2048];

// ---------------------------------------------------------------------------
// Kernel 1: window partition + LayerNorm1
// ---------------------------------------------------------------------------
__global__ void __launch_bounds__(128) ln1_part_k(
    const float* __restrict__ x, const float* __restrict__ gamma,
    const float* __restrict__ beta, float* __restrict__ t, float* __restrict__ xn)
{
    int tok = blockIdx.x;
    int tid = threadIdx.x;
    int b = tok >> 14;
    int n = (tok >> 6) & 255;
    int l = tok & 63;
    int h = ((n >> 4) << 3) | (l >> 3);
    int w = ((n & 15) << 3) | (l & 7);
    size_t base = ((size_t)b * 512) * 16384 + (size_t)(h << 7) + w;

    float v[4];
    float s = 0.f, s2 = 0.f;
#pragma unroll
    for (int k = 0; k < 4; k++) {
        int c = tid + (k << 7);
        v[k] = x[base + ((size_t)c << 14)];
        s += v[k]; s2 += v[k] * v[k];
    }
#pragma unroll
    for (int off = 16; off; off >>= 1) {
        s  += __shfl_xor_sync(0xffffffffu, s,  off);
        s2 += __shfl_xor_sync(0xffffffffu, s2, off);
    }
    __shared__ float sh[8];
    int wid = tid >> 5, lane = tid & 31;
    if (lane == 0) { sh[wid] = s; sh[4 + wid] = s2; }
    __syncthreads();
    s  = sh[0] + sh[1] + sh[2] + sh[3];
    s2 = sh[4] + sh[5] + sh[6] + sh[7];
    float mu  = s  * (1.f / 512.f);
    float var = s2 * (1.f / 512.f) - mu * mu;
    float rs  = rsqrtf(var + 1e-5f);

    size_t tb = (size_t)tok * 512;
#pragma unroll
    for (int k = 0; k < 4; k++) {
        int c = tid + (k << 7);
        t [tb + c] = v[k];
        xn[tb + c] = (v[k] - mu) * rs * gamma[c] + beta[c];
    }
}

// ---------------------------------------------------------------------------
// LayerNorm2
// ---------------------------------------------------------------------------
__global__ void __launch_bounds__(128) ln2_k(
    const float* __restrict__ src, const float* __restrict__ gamma,
    const float* __restrict__ beta, float* __restrict__ xn)
{
    int tok = blockIdx.x;
    int tid = threadIdx.x;
    size_t tb = (size_t)tok * 512;

    float v[4];
    float s = 0.f, s2 = 0.f;
#pragma unroll
    for (int k = 0; k < 4; k++) {
        int c = tid + (k << 7);
        v[k] = src[tb + c];
        s += v[k]; s2 += v[k] * v[k];
    }
#pragma unroll
    for (int off = 16; off; off >>= 1) {
        s  += __shfl_xor_sync(0xffffffffu, s,  off);
        s2 += __shfl_xor_sync(0xffffffffu, s2, off);
    }
    __shared__ float sh[8];
    int wid = tid >> 5, lane = tid & 31;
    if (lane == 0) { sh[wid] = s; sh[4 + wid] = s2; }
    __syncthreads();
    s  = sh[0] + sh[1] + sh[2] + sh[3];
    s2 = sh[4] + sh[5] + sh[6] + sh[7];
    float mu  = s  * (1.f / 512.f);
    float var = s2 * (1.f / 512.f) - mu * mu;
    float rs  = rsqrtf(var + 1e-5f);
#pragma unroll
    for (int k = 0; k < 4; k++) {
        int c = tid + (k << 7);
        xn[tb + c] = (v[k] - mu) * rs * gamma[c] + beta[c];
    }
}

// ---------------------------------------------------------------------------
// Attention: one CTA per (window, head)
// ---------------------------------------------------------------------------
__global__ void __launch_bounds__(256) attn_k(
    const float* __restrict__ qkv, float* __restrict__ o)
{
    __shared__ float ks[64][68];
    __shared__ float vs[64][68];

    int tid  = threadIdx.x;
    int win  = blockIdx.x >> 3;
    int head = blockIdx.x & 7;
    const float* base = qkv + (size_t)win * 64 * 1536 + head * 64;

    int row = tid >> 2;
    int q4  = tid & 3;
    int e0  = q4 << 4;

    {
        const float* kp = base + 512  + (size_t)row * 1536 + e0;
        const float* vp = base + 1024 + (size_t)row * 1536 + e0;
#pragma unroll
        for (int s = 0; s < 4; s++) {
            *(float4*)&ks[row][e0 + s * 4] = *(const float4*)(kp + s * 4);
            *(float4*)&vs[row][e0 + s * 4] = *(const float4*)(vp + s * 4);
        }
    }
    float qreg[16];
    {
        const float scl = 1.f / 4096.f;
        const float* qp = base + (size_t)row * 1536 + e0;
#pragma unroll
        for (int s = 0; s < 4; s++) {
            float4 q = *(const float4*)(qp + s * 4);
            qreg[s*4+0] = q.x * scl; qreg[s*4+1] = q.y * scl;
            qreg[s*4+2] = q.z * scl; qreg[s*4+3] = q.w * scl;
        }
    }
    __syncthreads();

    float p[64];
#pragma unroll
    for (int m = 0; m < 64; m++) {
        float acc = 0.f;
#pragma unroll
        for (int s = 0; s < 4; s++) {
            float4 kv = *(float4*)&ks[m][e0 + s * 4];
            acc += qreg[s*4+0] * kv.x + qreg[s*4+1] * kv.y
                 + qreg[s*4+2] * kv.z + qreg[s*4+3] * kv.w;
        }
        p[m] = acc;
    }
#pragma unroll
    for (int m = 0; m < 64; m++) {
        p[m] += __shfl_xor_sync(0xffffffffu, p[m], 1);
        p[m] += __shfl_xor_sync(0xffffffffu, p[m], 2);
    }
    float mx = -1e30f;
#pragma unroll
    for (int m = 0; m < 64; m++) mx = fmaxf(mx, p[m]);
    float sum = 0.f;
#pragma unroll
    for (int m = 0; m < 64; m++) { p[m] = expf(p[m] - mx); sum += p[m]; }
    float inv = 1.f / sum;

    float oa[16];
#pragma unroll
    for (int e = 0; e < 16; e++) oa[e] = 0.f;
#pragma unroll
    for (int m = 0; m < 64; m++) {
        float a = p[m] * inv;
#pragma unroll
        for (int s = 0; s < 4; s++) {
            float4 vv = *(float4*)&vs[m][e0 + s * 4];
            oa[s*4+0] += a * vv.x; oa[s*4+1] += a * vv.y;
            oa[s*4+2] += a * vv.z; oa[s*4+3] += a * vv.w;
        }
    }
    float* op = o + (size_t)win * 64 * 512 + (size_t)row * 512 + head * 64 + e0;
#pragma unroll
    for (int s = 0; s < 4; s++)
        *(float4*)(op + s * 4) = make_float4(oa[s*4+0], oa[s*4+1], oa[s*4+2], oa[s*4+3]);
}

// ---------------------------------------------------------------------------
// TF32 tensor-core GEMM: C[M,N] = A[M,K] @ B[K,N] (+bias, epilogue variants)
//   MODE 0: C = A@B + bias
//   MODE 1: C += A@B + bias
//   MODE 2: C = gelu_exact(A@B + bias)
//   MODE 3: out[x-layout] = C(residual) + A@B + bias  (fused un-partition)
// CTA tile 128x128, BK=16, 128 threads = 4 warps (2x2), warp tile 64x64.
// mma.sync.m16n8k8 tf32, cp.async double buffer.
// Conflict-free smem: As[128][20] (bank perm 20r+c), Bs[16][136] (8c+r).
// ---------------------------------------------------------------------------
#define AS_STRIDE 20
#define BS_STRIDE 136
#define AS_ELEMS (128 * AS_STRIDE)
#define BS_ELEMS (16 * BS_STRIDE)

__device__ __forceinline__ float gelu_exact(float v) {
    return 0.5f * v * (1.0f + erff(v * 0.70710678118654752440f));
}

__device__ __forceinline__ uint32_t f2tf(float f) {
    uint32_t u;
    asm("cvt.rna.tf32.f32 %0, %1;" : "=r"(u) : "f"(f));
    return u;
}

__device__ __forceinline__ void mma_tf32(float* d, const uint32_t* a, const uint32_t* b) {
    asm volatile(
        "mma.sync.aligned.m16n8k8.row.col.f32.tf32.tf32.f32 "
        "{%0,%1,%2,%3}, {%4,%5,%6,%7}, {%8,%9}, {%0,%1,%2,%3};"
        : "+f"(d[0]), "+f"(d[1]), "+f"(d[2]), "+f"(d[3])
        : "r"(a[0]), "r"(a[1]), "r"(a[2]), "r"(a[3]), "r"(b[0]), "r"(b[1]));
}

__device__ __forceinline__ void cpa16(uint32_t dst, const float* src) {
    asm volatile("cp.async.cg.shared.global [%0], [%1], 16;" :: "r"(dst), "l"(src));
}
__device__ __forceinline__ void cp_commit() {
    asm volatile("cp.async.commit_group;");
}
template <int N_>
__device__ __forceinline__ void cp_wait() {
    asm volatile("cp.async.wait_group %0;" :: "n"(N_));
}

template <int MODE>
__global__ void __launch_bounds__(128, 2) tgemm_k(
    const float* __restrict__ A, const float* __restrict__ B,
    const float* __restrict__ bias, float* __restrict__ C,
    float* __restrict__ out, int M, int N, int K)
{
    __shared__ float As[2][AS_ELEMS];
    __shared__ float Bs[2][BS_ELEMS];

    int tid   = threadIdx.x;
    int lane  = tid & 31;
    int warp  = tid >> 5;
    int warpM = warp >> 1;   // 0..1
    int warpN = warp & 1;    // 0..1
    int row0  = blockIdx.y << 7;
    int col0  = blockIdx.x << 7;

    uint32_t as_base = (uint32_t)__cvta_generic_to_shared(&As[0][0]);
    uint32_t bs_base = (uint32_t)__cvta_generic_to_shared(&Bs[0][0]);

    // A loader: thread tid handles row tid, 16 cols (4x cp.async 16B)
    const float* Agp = A + (size_t)(row0 + tid) * K;
    uint32_t a_dst0 = as_base + (uint32_t)(tid * AS_STRIDE) * 4u;
    // B loader: row = tid>>3 (0..15), col chunk = (tid&7)*16
    int brow = tid >> 3, bcol = (tid & 7) << 4;
    const float* Bgp = B + (size_t)brow * N + col0 + bcol;
    uint32_t b_dst0 = bs_base + (uint32_t)(brow * BS_STRIDE + bcol) * 4u;

    int niter = K >> 4;

    // prefetch iter 0 into buffer 0
    {
#pragma unroll
        for (int s = 0; s < 4; s++) cpa16(a_dst0 + s * 16, Agp + s * 4);
#pragma unroll
        for (int s = 0; s < 4; s++) cpa16(b_dst0 + s * 16, Bgp + s * 4);
        cp_commit();
    }

    float acc[4][8][4];
#pragma unroll
    for (int mt = 0; mt < 4; mt++)
#pragma unroll
        for (int nt = 0; nt < 8; nt++)
#pragma unroll
            for (int e = 0; e < 4; e++) acc[mt][nt][e] = 0.f;

    int r = lane >> 2;   // 0..7
    int c = lane & 3;    // 0..3

    for (int it = 0; it < niter; it++) {
        int buf = it & 1;
        if (it + 1 < niter) {
            int nb = buf ^ 1;
            int k0 = (it + 1) << 4;
            uint32_t ad = a_dst0 + (uint32_t)(nb * AS_ELEMS) * 4u;
            const float* ag = Agp + k0;
#pragma unroll
            for (int s = 0; s < 4; s++) cpa16(ad + s * 16, ag + s * 4);
            uint32_t bd = b_dst0 + (uint32_t)(nb * BS_ELEMS) * 4u;
            const float* bg = Bgp + (size_t)k0 * N;
#pragma unroll
            for (int s = 0; s < 4; s++) cpa16(bd + s * 16, bg + s * 4);
            cp_commit();
            cp_wait<1>();
        } else {
            cp_wait<0>();
        }
        __syncthreads();

        const float* as = &As[buf][warpM * 64 * AS_STRIDE];
        const float* bs = &Bs[buf][warpN * 64];

#pragma unroll
        for (int ks = 0; ks < 16; ks += 8) {
            uint32_t af[4][4];
#pragma unroll
            for (int mt = 0; mt < 4; mt++) {
                int rowa = mt * 16 + r;
                af[mt][0] = f2tf(as[(rowa    ) * AS_STRIDE + ks + c    ]);
                af[mt][1] = f2tf(as[(rowa + 8) * AS_STRIDE + ks + c    ]);
                af[mt][2] = f2tf(as[(rowa    ) * AS_STRIDE + ks + c + 4]);
                af[mt][3] = f2tf(as[(rowa + 8) * AS_STRIDE + ks + c + 4]);
            }
            uint32_t bf[8][2];
#pragma unroll
            for (int nt = 0; nt < 8; nt++) {
                bf[nt][0] = f2tf(bs[(ks + c    ) * BS_STRIDE + nt * 8 + r]);
                bf[nt][1] = f2tf(bs[(ks + c + 4) * BS_STRIDE + nt * 8 + r]);
            }
#pragma unroll
            for (int mt = 0; mt < 4; mt++)
#pragma unroll
                for (int nt = 0; nt < 8; nt++)
                    mma_tf32(acc[mt][nt], af[mt], bf[nt]);
        }
        __syncthreads();
    }

    // ---- epilogue ----
    int c2 = c << 1;
#pragma unroll
    for (int nt = 0; nt < 8; nt++) {
        int gcol = col0 + warpN * 64 + nt * 8 + c2;
        float b0 = bias[gcol], b1 = bias[gcol + 1];
#pragma unroll
        for (int mt = 0; mt < 4; mt++) {
            int grow = row0 + warpM * 64 + mt * 16 + r;
#pragma unroll
            for (int half = 0; half < 2; half++) {
                int rr = grow + half * 8;
                float v0 = acc[mt][nt][half * 2 + 0] + b0;
                float v1 = acc[mt][nt][half * 2 + 1] + b1;
                if (MODE == 0) {
                    *(float2*)&C[(size_t)rr * N + gcol] = make_float2(v0, v1);
                } else if (MODE == 2) {
                    *(float2*)&C[(size_t)rr * N + gcol] =
                        make_float2(gelu_exact(v0), gelu_exact(v1));
                } else if (MODE == 1) {
                    float2 cur = *(float2*)&C[(size_t)rr * N + gcol];
                    cur.x += v0; cur.y += v1;
                    *(float2*)&C[(size_t)rr * N + gcol] = cur;
                } else { // MODE 3
                    float2 res = *(float2*)&C[(size_t)rr * N + gcol];
                    int b  = rr >> 14;
                    int n  = (rr >> 6) & 255;
                    int l  = rr & 63;
                    int hh = ((n >> 4) << 3) | (l >> 3);
                    int ww = ((n & 15) << 3) | (l & 7);
                    size_t sbase = ((size_t)(b * 512) << 14) + (size_t)(hh << 7) + ww;
                    out[sbase + ((size_t)gcol << 14)]       = v0 + res.x;
                    out[sbase + ((size_t)(gcol + 1) << 14)] = v1 + res.y;
                }
            }
        }
    }
}

// ---------------------------------------------------------------------------
// Launch sequence
// ---------------------------------------------------------------------------
extern "C" void kernel_launch(void* const* d_in, const int* in_sizes, int n_in,
                              void* d_out, int out_size)
{
    const float* x     = (const float*)d_in[0];
    const float* g1    = (const float*)d_in[1];
    const float* be1   = (const float*)d_in[2];
    const float* g2    = (const float*)d_in[3];
    const float* be2   = (const float*)d_in[4];
    const float* w_qkv = (const float*)d_in[5];
    const float* b_qkv = (const float*)d_in[6];
    const float* w_out = (const float*)d_in[7];
    const float* b_out = (const float*)d_in[8];
    const float* w1    = (const float*)d_in[9];
    const float* b1m   = (const float*)d_in[10];
    const float* w2    = (const float*)d_in[11];
    const float* b2m   = (const float*)d_in[12];
    float* out = (float*)d_out;

    float *t, *xn, *qkv, *o, *hbuf;
    cudaGetSymbolAddress((void**)&t,    g_t);
    cudaGetSymbolAddress((void**)&xn,   g_xn);
    cudaGetSymbolAddress((void**)&qkv,  g_qkv);
    cudaGetSymbolAddress((void**)&o,    g_o);
    cudaGetSymbolAddress((void**)&hbuf, g_h);

    // 1. window partition + LN1
    ln1_part_k<<<TOKS, 128>>>(x, g1, be1, t, xn);
    // 2. qkv = xn @ w_qkv + b_qkv
    tgemm_k<0><<<dim3(1536 / 128, TOKS / 128), 128>>>(xn, w_qkv, b_qkv, qkv, nullptr, TOKS, 1536, 512);
    // 3. windowed attention
    attn_k<<<(TOKS / 64) * 8, 256>>>(qkv, o);
    // 4. t += o @ w_out + b_out
    tgemm_k<1><<<dim3(512 / 128, TOKS / 128), 128>>>(o, w_out, b_out, t, nullptr, TOKS, 512, 512);
    // 5. LN2
    ln2_k<<<TOKS, 128>>>(t, g2, be2, xn);
    // 6. h = gelu(xn @ w1 + b1)
    tgemm_k<2><<<dim3(2048 / 128, TOKS / 128), 128>>>(xn, w1, b1m, hbuf, nullptr, TOKS, 2048, 512);
    // 7. out[x-layout] = t + h @ w2 + b2  (fused un-partition)
    tgemm_k<3><<<dim3(512 / 128, TOKS / 128), 128>>>(hbuf, w2, b2m, t, out, TOKS, 512, 2048);
}

// round 3
// speedup vs baseline: 2.5621x; 1.4189x over previous
#include <cuda_runtime.h>
#include <math.h>
#include <stdint.h>

// ---------------------------------------------------------------------------
// B=8, C=512, H=W=128, WS=8, NH=8, hd=64, L=64, N=256 windows/batch
// TOKS = 8*256*64 = 131072
// ---------------------------------------------------------------------------
#define TOKS 131072

// Scratch (device globals — no cudaMalloc allowed)
__device__ float g_t  [(size_t)TOKS * 512];
__device__ float g_xn [(size_t)TOKS * 512];
__device__ float g_qkv[(size_t)TOKS * 1536];
__device__ float g_o  [(size_t)TOKS * 512];
__device__ float g_h  [(size_t)TOKS * 2048];
// tf32-rounded weights: w_qkv(512*1536) w_out(512*512) w1(512*2048) w2(2048*512)
#define WQKV_OFF 0
#define WOUT_OFF (512 * 1536)
#define W1_OFF   (WOUT_OFF + 512 * 512)
#define W2_OFF   (W1_OFF + 512 * 2048)
#define WTOT     (W2_OFF + 2048 * 512)
__device__ float g_w  [WTOT];

__device__ __forceinline__ uint32_t f2tf(float f) {
    uint32_t u;
    asm("cvt.rna.tf32.f32 %0, %1;" : "=r"(u) : "f"(f));
    return u;
}
__device__ __forceinline__ float tf32r(float f) { return __uint_as_float(f2tf(f)); }

// ---------------------------------------------------------------------------
// Weight rounding: one pass, float4
// ---------------------------------------------------------------------------
__global__ void __launch_bounds__(256) wround_k(
    const float* __restrict__ wqkv, const float* __restrict__ wout,
    const float* __restrict__ w1, const float* __restrict__ w2,
    float* __restrict__ dst)
{
    int i = (blockIdx.x * 256 + threadIdx.x) * 4;
    const float* src;
    int off = i;
    if (i < WOUT_OFF)      { src = wqkv; off = i; }
    else if (i < W1_OFF)   { src = wout; off = i - WOUT_OFF; }
    else if (i < W2_OFF)   { src = w1;   off = i - W1_OFF; }
    else                   { src = w2;   off = i - W2_OFF; }
    float4 v = *(const float4*)(src + off);
    v.x = tf32r(v.x); v.y = tf32r(v.y); v.z = tf32r(v.z); v.w = tf32r(v.w);
    *(float4*)(dst + i) = v;
}

// ---------------------------------------------------------------------------
// Kernel 1: window partition + LayerNorm1 (xn rounded to tf32)
// ---------------------------------------------------------------------------
__global__ void __launch_bounds__(128) ln1_part_k(
    const float* __restrict__ x, const float* __restrict__ gamma,
    const float* __restrict__ beta, float* __restrict__ t, float* __restrict__ xn)
{
    int tok = blockIdx.x;
    int tid = threadIdx.x;
    int b = tok >> 14;
    int n = (tok >> 6) & 255;
    int l = tok & 63;
    int h = ((n >> 4) << 3) | (l >> 3);
    int w = ((n & 15) << 3) | (l & 7);
    size_t base = ((size_t)b * 512) * 16384 + (size_t)(h << 7) + w;

    float v[4];
    float s = 0.f, s2 = 0.f;
#pragma unroll
    for (int k = 0; k < 4; k++) {
        int c = tid + (k << 7);
        v[k] = x[base + ((size_t)c << 14)];
        s += v[k]; s2 += v[k] * v[k];
    }
#pragma unroll
    for (int off = 16; off; off >>= 1) {
        s  += __shfl_xor_sync(0xffffffffu, s,  off);
        s2 += __shfl_xor_sync(0xffffffffu, s2, off);
    }
    __shared__ float sh[8];
    int wid = tid >> 5, lane = tid & 31;
    if (lane == 0) { sh[wid] = s; sh[4 + wid] = s2; }
    __syncthreads();
    s  = sh[0] + sh[1] + sh[2] + sh[3];
    s2 = sh[4] + sh[5] + sh[6] + sh[7];
    float mu  = s  * (1.f / 512.f);
    float var = s2 * (1.f / 512.f) - mu * mu;
    float rs  = rsqrtf(var + 1e-5f);

    size_t tb = (size_t)tok * 512;
#pragma unroll
    for (int k = 0; k < 4; k++) {
        int c = tid + (k << 7);
        t [tb + c] = v[k];
        xn[tb + c] = tf32r((v[k] - mu) * rs * gamma[c] + beta[c]);
    }
}

// ---------------------------------------------------------------------------
// LayerNorm2 (xn rounded to tf32)
// ---------------------------------------------------------------------------
__global__ void __launch_bounds__(128) ln2_k(
    const float* __restrict__ src, const float* __restrict__ gamma,
    const float* __restrict__ beta, float* __restrict__ xn)
{
    int tok = blockIdx.x;
    int tid = threadIdx.x;
    size_t tb = (size_t)tok * 512;

    float v[4];
    float s = 0.f, s2 = 0.f;
#pragma unroll
    for (int k = 0; k < 4; k++) {
        int c = tid + (k << 7);
        v[k] = src[tb + c];
        s += v[k]; s2 += v[k] * v[k];
    }
#pragma unroll
    for (int off = 16; off; off >>= 1) {
        s  += __shfl_xor_sync(0xffffffffu, s,  off);
        s2 += __shfl_xor_sync(0xffffffffu, s2, off);
    }
    __shared__ float sh[8];
    int wid = tid >> 5, lane = tid & 31;
    if (lane == 0) { sh[wid] = s; sh[4 + wid] = s2; }
    __syncthreads();
    s  = sh[0] + sh[1] + sh[2] + sh[3];
    s2 = sh[4] + sh[5] + sh[6] + sh[7];
    float mu  = s  * (1.f / 512.f);
    float var = s2 * (1.f / 512.f) - mu * mu;
    float rs  = rsqrtf(var + 1e-5f);
#pragma unroll
    for (int k = 0; k < 4; k++) {
        int c = tid + (k << 7);
        xn[tb + c] = tf32r((v[k] - mu) * rs * gamma[c] + beta[c]);
    }
}

// ---------------------------------------------------------------------------
// Attention: one CTA per (window, head). Output rounded to tf32.
// ---------------------------------------------------------------------------
__global__ void __launch_bounds__(256) attn_k(
    const float* __restrict__ qkv, float* __restrict__ o)
{
    __shared__ float ks[64][68];
    __shared__ float vs[64][68];

    int tid  = threadIdx.x;
    int win  = blockIdx.x >> 3;
    int head = blockIdx.x & 7;
    const float* base = qkv + (size_t)win * 64 * 1536 + head * 64;

    int row = tid >> 2;
    int q4  = tid & 3;
    int e0  = q4 << 4;

    {
        const float* kp = base + 512  + (size_t)row * 1536 + e0;
        const float* vp = base + 1024 + (size_t)row * 1536 + e0;
#pragma unroll
        for (int s = 0; s < 4; s++) {
            *(float4*)&ks[row][e0 + s * 4] = *(const float4*)(kp + s * 4);
            *(float4*)&vs[row][e0 + s * 4] = *(const float4*)(vp + s * 4);
        }
    }
    float qreg[16];
    {
        const float scl = 1.f / 4096.f;
        const float* qp = base + (size_t)row * 1536 + e0;
#pragma unroll
        for (int s = 0; s < 4; s++) {
            float4 q = *(const float4*)(qp + s * 4);
            qreg[s*4+0] = q.x * scl; qreg[s*4+1] = q.y * scl;
            qreg[s*4+2] = q.z * scl; qreg[s*4+3] = q.w * scl;
        }
    }
    __syncthreads();

    float p[64];
#pragma unroll
    for (int m = 0; m < 64; m++) {
        float acc = 0.f;
#pragma unroll
        for (int s = 0; s < 4; s++) {
            float4 kv = *(float4*)&ks[m][e0 + s * 4];
            acc += qreg[s*4+0] * kv.x + qreg[s*4+1] * kv.y
                 + qreg[s*4+2] * kv.z + qreg[s*4+3] * kv.w;
        }
        p[m] = acc;
    }
#pragma unroll
    for (int m = 0; m < 64; m++) {
        p[m] += __shfl_xor_sync(0xffffffffu, p[m], 1);
        p[m] += __shfl_xor_sync(0xffffffffu, p[m], 2);
    }
    float mx = -1e30f;
#pragma unroll
    for (int m = 0; m < 64; m++) mx = fmaxf(mx, p[m]);
    float sum = 0.f;
#pragma unroll
    for (int m = 0; m < 64; m++) { p[m] = expf(p[m] - mx); sum += p[m]; }
    float inv = 1.f / sum;

    float oa[16];
#pragma unroll
    for (int e = 0; e < 16; e++) oa[e] = 0.f;
#pragma unroll
    for (int m = 0; m < 64; m++) {
        float a = p[m] * inv;
#pragma unroll
        for (int s = 0; s < 4; s++) {
            float4 vv = *(float4*)&vs[m][e0 + s * 4];
            oa[s*4+0] += a * vv.x; oa[s*4+1] += a * vv.y;
            oa[s*4+2] += a * vv.z; oa[s*4+3] += a * vv.w;
        }
    }
    float* op = o + (size_t)win * 64 * 512 + (size_t)row * 512 + head * 64 + e0;
#pragma unroll
    for (int s = 0; s < 4; s++)
        *(float4*)(op + s * 4) = make_float4(tf32r(oa[s*4+0]), tf32r(oa[s*4+1]),
                                             tf32r(oa[s*4+2]), tf32r(oa[s*4+3]));
}

// ---------------------------------------------------------------------------
// TF32 tensor-core GEMM. Inputs MUST be pre-rounded to tf32 bit patterns.
//   MODE 0: C = A@B + bias
//   MODE 1: C += A@B + bias
//   MODE 2: C = tf32r(gelu_exact(A@B + bias))
//   MODE 3: out[x-layout] = C(residual) + A@B + bias
// CTA 128x128, BK=16, 256 threads = 8 warps (2M x 4N), warp tile 64x32.
// mma.sync.m16n8k8, cp.async double buffer, conflict-free smem permutations.
// ---------------------------------------------------------------------------
#define AS_STRIDE 20
#define BS_STRIDE 136
#define AS_ELEMS (128 * AS_STRIDE)
#define BS_ELEMS (16 * BS_STRIDE)

__device__ __forceinline__ float gelu_exact(float v) {
    return 0.5f * v * (1.0f + erff(v * 0.70710678118654752440f));
}

__device__ __forceinline__ void mma_tf32(float* d, const uint32_t* a, const uint32_t* b) {
    asm volatile(
        "mma.sync.aligned.m16n8k8.row.col.f32.tf32.tf32.f32 "
        "{%0,%1,%2,%3}, {%4,%5,%6,%7}, {%8,%9}, {%0,%1,%2,%3};"
        : "+f"(d[0]), "+f"(d[1]), "+f"(d[2]), "+f"(d[3])
        : "r"(a[0]), "r"(a[1]), "r"(a[2]), "r"(a[3]), "r"(b[0]), "r"(b[1]));
}

__device__ __forceinline__ void cpa16(uint32_t dst, const float* src) {
    asm volatile("cp.async.cg.shared.global [%0], [%1], 16;" :: "r"(dst), "l"(src));
}
__device__ __forceinline__ void cp_commit() {
    asm volatile("cp.async.commit_group;");
}
template <int N_>
__device__ __forceinline__ void cp_wait() {
    asm volatile("cp.async.wait_group %0;" :: "n"(N_));
}

template <int MODE>
__global__ void __launch_bounds__(256, 2) tgemm_k(
    const float* __restrict__ A, const float* __restrict__ B,
    const float* __restrict__ bias, float* __restrict__ C,
    float* __restrict__ out, int M, int N, int K)
{
    __shared__ float As[2][AS_ELEMS];
    __shared__ float Bs[2][BS_ELEMS];

    int tid   = threadIdx.x;
    int lane  = tid & 31;
    int warp  = tid >> 5;
    int warpM = warp >> 2;   // 0..1  (64-row slab)
    int warpN = warp & 3;    // 0..3  (32-col slab)
    int row0  = blockIdx.y << 7;
    int col0  = blockIdx.x << 7;

    uint32_t as_base = (uint32_t)__cvta_generic_to_shared(&As[0][0]);
    uint32_t bs_base = (uint32_t)__cvta_generic_to_shared(&Bs[0][0]);

    // A loaders: 512 float4 (128 rows x 4 chunks); thread handles f = tid, tid+256
    int af0_r = tid >> 2,        af0_c = (tid & 3) << 2;
    int af1_r = (tid + 256) >> 2, af1_c = af0_c;
    const float* Ag0 = A + (size_t)(row0 + af0_r) * K + af0_c;
    const float* Ag1 = A + (size_t)(row0 + af1_r) * K + af1_c;
    uint32_t a_d0 = as_base + (uint32_t)(af0_r * AS_STRIDE + af0_c) * 4u;
    uint32_t a_d1 = as_base + (uint32_t)(af1_r * AS_STRIDE + af1_c) * 4u;
    // B loaders: 512 float4 (16 rows x 32 chunks); f = tid, tid+256
    int bf0_r = tid >> 5,        bf0_c = (tid & 31) << 2;
    int bf1_r = bf0_r + 8,       bf1_c = bf0_c;
    const float* Bg0 = B + (size_t)bf0_r * N + col0 + bf0_c;
    const float* Bg1 = B + (size_t)bf1_r * N + col0 + bf1_c;
    uint32_t b_d0 = bs_base + (uint32_t)(bf0_r * BS_STRIDE + bf0_c) * 4u;
    uint32_t b_d1 = bs_base + (uint32_t)(bf1_r * BS_STRIDE + bf1_c) * 4u;

    int niter = K >> 4;

    // prefetch iter 0 into buffer 0
    cpa16(a_d0, Ag0);
    cpa16(a_d1, Ag1);
    cpa16(b_d0, Bg0);
    cpa16(b_d1, Bg1);
    cp_commit();

    float acc[4][4][4];
#pragma unroll
    for (int mt = 0; mt < 4; mt++)
#pragma unroll
        for (int nt = 0; nt < 4; nt++)
#pragma unroll
            for (int e = 0; e < 4; e++) acc[mt][nt][e] = 0.f;

    int r = lane >> 2;   // 0..7
    int c = lane & 3;    // 0..3

    for (int it = 0; it < niter; it++) {
        int buf = it & 1;
        if (it + 1 < niter) {
            int nb = buf ^ 1;
            int k0 = (it + 1) << 4;
            uint32_t ao = (uint32_t)(nb * AS_ELEMS) * 4u;
            uint32_t bo = (uint32_t)(nb * BS_ELEMS) * 4u;
            cpa16(a_d0 + ao, Ag0 + k0);
            cpa16(a_d1 + ao, Ag1 + k0);
            cpa16(b_d0 + bo, Bg0 + (size_t)k0 * N);
            cpa16(b_d1 + bo, Bg1 + (size_t)k0 * N);
            cp_commit();
            cp_wait<1>();
        } else {
            cp_wait<0>();
        }
        __syncthreads();

        const float* as = &As[buf][warpM * 64 * AS_STRIDE];
        const float* bs = &Bs[buf][warpN * 32];

#pragma unroll
        for (int ks = 0; ks < 16; ks += 8) {
            uint32_t af[4][4];
#pragma unroll
            for (int mt = 0; mt < 4; mt++) {
                int rowa = mt * 16 + r;
                af[mt][0] = __float_as_uint(as[(rowa    ) * AS_STRIDE + ks + c    ]);
                af[mt][1] = __float_as_uint(as[(rowa + 8) * AS_STRIDE + ks + c    ]);
                af[mt][2] = __float_as_uint(as[(rowa    ) * AS_STRIDE + ks + c + 4]);
                af[mt][3] = __float_as_uint(as[(rowa + 8) * AS_STRIDE + ks + c + 4]);
            }
            uint32_t bf[4][2];
#pragma unroll
            for (int nt = 0; nt < 4; nt++) {
                bf[nt][0] = __float_as_uint(bs[(ks + c    ) * BS_STRIDE + nt * 8 + r]);
                bf[nt][1] = __float_as_uint(bs[(ks + c + 4) * BS_STRIDE + nt * 8 + r]);
            }
#pragma unroll
            for (int mt = 0; mt < 4; mt++)
#pragma unroll
                for (int nt = 0; nt < 4; nt++)
                    mma_tf32(acc[mt][nt], af[mt], bf[nt]);
        }
        __syncthreads();
    }

    // ---- epilogue ----
    int c2 = c << 1;
#pragma unroll
    for (int nt = 0; nt < 4; nt++) {
        int gcol = col0 + warpN * 32 + nt * 8 + c2;
        float b0 = bias[gcol], b1 = bias[gcol + 1];
#pragma unroll
        for (int mt = 0; mt < 4; mt++) {
            int grow = row0 + warpM * 64 + mt * 16 + r;
#pragma unroll
            for (int half = 0; half < 2; half++) {
                int rr = grow + half * 8;
                float v0 = acc[mt][nt][half * 2 + 0] + b0;
                float v1 = acc[mt][nt][half * 2 + 1] + b1;
                if (MODE == 0) {
                    *(float2*)&C[(size_t)rr * N + gcol] = make_float2(v0, v1);
                } else if (MODE == 2) {
                    *(float2*)&C[(size_t)rr * N + gcol] =
                        make_float2(tf32r(gelu_exact(v0)), tf32r(gelu_exact(v1)));
                } else if (MODE == 1) {
                    float2 cur = *(float2*)&C[(size_t)rr * N + gcol];
                    cur.x += v0; cur.y += v1;
                    *(float2*)&C[(size_t)rr * N + gcol] = cur;
                } else { // MODE 3
                    float2 res = *(float2*)&C[(size_t)rr * N + gcol];
                    int b  = rr >> 14;
                    int n  = (rr >> 6) & 255;
                    int l  = rr & 63;
                    int hh = ((n >> 4) << 3) | (l >> 3);
                    int ww = ((n & 15) << 3) | (l & 7);
                    size_t sbase = ((size_t)(b * 512) << 14) + (size_t)(hh << 7) + ww;
                    out[sbase + ((size_t)gcol << 14)]       = v0 + res.x;
                    out[sbase + ((size_t)(gcol + 1) << 14)] = v1 + res.y;
                }
            }
        }
    }
}

// ---------------------------------------------------------------------------
// Launch sequence
// ---------------------------------------------------------------------------
extern "C" void kernel_launch(void* const* d_in, const int* in_sizes, int n_in,
                              void* d_out, int out_size)
{
    const float* x     = (const float*)d_in[0];
    const float* g1    = (const float*)d_in[1];
    const float* be1   = (const float*)d_in[2];
    const float* g2    = (const float*)d_in[3];
    const float* be2   = (const float*)d_in[4];
    const float* w_qkv = (const float*)d_in[5];
    const float* b_qkv = (const float*)d_in[6];
    const float* w_out = (const float*)d_in[7];
    const float* b_out = (const float*)d_in[8];
    const float* w1    = (const float*)d_in[9];
    const float* b1m   = (const float*)d_in[10];
    const float* w2    = (const float*)d_in[11];
    const float* b2m   = (const float*)d_in[12];
    float* out = (float*)d_out;

    float *t, *xn, *qkv, *o, *hbuf, *wr;
    cudaGetSymbolAddress((void**)&t,    g_t);
    cudaGetSymbolAddress((void**)&xn,   g_xn);
    cudaGetSymbolAddress((void**)&qkv,  g_qkv);
    cudaGetSymbolAddress((void**)&o,    g_o);
    cudaGetSymbolAddress((void**)&hbuf, g_h);
    cudaGetSymbolAddress((void**)&wr,   g_w);

    // 0. round weights to tf32 (12.6 MB, ~6us)
    wround_k<<<WTOT / (256 * 4), 256>>>(w_qkv, w_out, w1, w2, wr);
    // 1. window partition + LN1
    ln1_part_k<<<TOKS, 128>>>(x, g1, be1, t, xn);
    // 2. qkv = xn @ w_qkv + b_qkv
    tgemm_k<0><<<dim3(1536 / 128, TOKS / 128), 256>>>(xn, wr + WQKV_OFF, b_qkv, qkv, nullptr, TOKS, 1536, 512);
    // 3. windowed attention
    attn_k<<<(TOKS / 64) * 8, 256>>>(qkv, o);
    // 4. t += o @ w_out + b_out
    tgemm_k<1><<<dim3(512 / 128, TOKS / 128), 256>>>(o, wr + WOUT_OFF, b_out, t, nullptr, TOKS, 512, 512);
    // 5. LN2
    ln2_k<<<TOKS, 128>>>(t, g2, be2, xn);
    // 6. h = gelu(xn @ w1 + b1)
    tgemm_k<2><<<dim3(2048 / 128, TOKS / 128), 256>>>(xn, wr + W1_OFF, b1m, hbuf, nullptr, TOKS, 2048, 512);
    // 7. out[x-layout] = t + h @ w2 + b2  (fused un-partition)
    tgemm_k<3><<<dim3(512 / 128, TOKS / 128), 256>>>(hbuf, wr + W2_OFF, b2m, t, out, TOKS, 512, 2048);
}

// round 4
// speedup vs baseline: 4.5355x; 1.7702x over previous
#include <cuda_runtime.h>
#include <math.h>
#include <stdint.h>

// ---------------------------------------------------------------------------
// B=8, C=512, H=W=128, WS=8, NH=8, hd=64, L=64, N=256 windows/batch
// TOKS = 8*256*64 = 131072
// Activations bf16 (packed 2/word); residual stream t stays fp32.
// ---------------------------------------------------------------------------
#define TOKS 131072

__device__ float    g_t  [(size_t)TOKS * 512];   // residual (fp32)
__device__ uint32_t g_xn [(size_t)TOKS * 256];   // LN out (bf16x2)
__device__ uint32_t g_qkv[(size_t)TOKS * 768];   // qkv (bf16x2)
__device__ uint32_t g_o  [(size_t)TOKS * 256];   // attn out (bf16x2)
__device__ uint32_t g_h  [(size_t)TOKS * 1024];  // mlp hidden (bf16x2)

// weights packed as k-pair bf16 words: word(kp,n) = (bf16 w[2kp][n], bf16 w[2kp+1][n])
#define WQKV_OFF 0
#define WOUT_OFF 393216
#define W1_OFF   524288
#define W2_OFF   1048576
#define WTOT     1572864
__device__ uint32_t g_w[WTOT];

__device__ __forceinline__ uint32_t packbf(float lo, float hi) {
    uint32_t u;
    asm("cvt.rn.bf16x2.f32 %0, %1, %2;" : "=r"(u) : "f"(hi), "f"(lo));
    return u;
}
__device__ __forceinline__ float bflo(uint32_t w) { return __uint_as_float(w << 16); }
__device__ __forceinline__ float bfhi(uint32_t w) { return __uint_as_float(w & 0xffff0000u); }

// ---------------------------------------------------------------------------
// Weight pack: fp32 [K][N] -> bf16-pair words [K/2][N]
// ---------------------------------------------------------------------------
__global__ void __launch_bounds__(256) wpack_k(
    const float* __restrict__ wqkv, const float* __restrict__ wout,
    const float* __restrict__ w1, const float* __restrict__ w2,
    uint32_t* __restrict__ dst)
{
    int idx = blockIdx.x * 256 + threadIdx.x;
    float lo, hi;
    if (idx < WOUT_OFF) {
        int kp = idx / 1536, n = idx - kp * 1536;
        lo = wqkv[(2 * kp) * 1536 + n]; hi = wqkv[(2 * kp + 1) * 1536 + n];
    } else if (idx < W1_OFF) {
        int l = idx - WOUT_OFF; int kp = l >> 9, n = l & 511;
        lo = wout[(2 * kp) * 512 + n]; hi = wout[(2 * kp + 1) * 512 + n];
    } else if (idx < W2_OFF) {
        int l = idx - W1_OFF; int kp = l >> 11, n = l & 2047;
        lo = w1[(2 * kp) * 2048 + n]; hi = w1[(2 * kp + 1) * 2048 + n];
    } else {
        int l = idx - W2_OFF; int kp = l >> 9, n = l & 511;
        lo = w2[(2 * kp) * 512 + n]; hi = w2[(2 * kp + 1) * 512 + n];
    }
    dst[idx] = packbf(lo, hi);
}

// ---------------------------------------------------------------------------
// Window partition + LayerNorm1: t fp32, xn bf16
// ---------------------------------------------------------------------------
__global__ void __launch_bounds__(128) ln1_part_k(
    const float* __restrict__ x, const float* __restrict__ gamma,
    const float* __restrict__ beta, float* __restrict__ t, uint32_t* __restrict__ xn)
{
    int tok = blockIdx.x;
    int tid = threadIdx.x;
    int b = tok >> 14;
    int n = (tok >> 6) & 255;
    int l = tok & 63;
    int h = ((n >> 4) << 3) | (l >> 3);
    int w = ((n & 15) << 3) | (l & 7);
    size_t base = ((size_t)b * 512) * 16384 + (size_t)(h << 7) + w;

    int c0 = tid << 2;
    float v[4];
    float s = 0.f, s2 = 0.f;
#pragma unroll
    for (int k = 0; k < 4; k++) {
        v[k] = x[base + ((size_t)(c0 + k) << 14)];
        s += v[k]; s2 += v[k] * v[k];
    }
#pragma unroll
    for (int off = 16; off; off >>= 1) {
        s  += __shfl_xor_sync(0xffffffffu, s,  off);
        s2 += __shfl_xor_sync(0xffffffffu, s2, off);
    }
    __shared__ float sh[8];
    int wid = tid >> 5, lane = tid & 31;
    if (lane == 0) { sh[wid] = s; sh[4 + wid] = s2; }
    __syncthreads();
    s  = sh[0] + sh[1] + sh[2] + sh[3];
    s2 = sh[4] + sh[5] + sh[6] + sh[7];
    float mu  = s  * (1.f / 512.f);
    float var = s2 * (1.f / 512.f) - mu * mu;
    float rs  = rsqrtf(var + 1e-5f);

    float nv[4];
#pragma unroll
    for (int k = 0; k < 4; k++)
        nv[k] = (v[k] - mu) * rs * gamma[c0 + k] + beta[c0 + k];

    *(float4*)&t[(size_t)tok * 512 + c0] = make_float4(v[0], v[1], v[2], v[3]);
    uint2 pw = make_uint2(packbf(nv[0], nv[1]), packbf(nv[2], nv[3]));
    *(uint2*)&xn[(size_t)tok * 256 + (tid << 1)] = pw;
}

// ---------------------------------------------------------------------------
// LayerNorm2: fp32 src (t) -> bf16 xn
// ---------------------------------------------------------------------------
__global__ void __launch_bounds__(128) ln2_k(
    const float* __restrict__ src, const float* __restrict__ gamma,
    const float* __restrict__ beta, uint32_t* __restrict__ xn)
{
    int tok = blockIdx.x;
    int tid = threadIdx.x;
    int c0 = tid << 2;
    float4 v4 = *(const float4*)&src[(size_t)tok * 512 + c0];
    float v[4] = {v4.x, v4.y, v4.z, v4.w};
    float s = v[0] + v[1] + v[2] + v[3];
    float s2 = v[0]*v[0] + v[1]*v[1] + v[2]*v[2] + v[3]*v[3];
#pragma unroll
    for (int off = 16; off; off >>= 1) {
        s  += __shfl_xor_sync(0xffffffffu, s,  off);
        s2 += __shfl_xor_sync(0xffffffffu, s2, off);
    }
    __shared__ float sh[8];
    int wid = tid >> 5, lane = tid & 31;
    if (lane == 0) { sh[wid] = s; sh[4 + wid] = s2; }
    __syncthreads();
    s  = sh[0] + sh[1] + sh[2] + sh[3];
    s2 = sh[4] + sh[5] + sh[6] + sh[7];
    float mu  = s  * (1.f / 512.f);
    float var = s2 * (1.f / 512.f) - mu * mu;
    float rs  = rsqrtf(var + 1e-5f);

    float nv[4];
#pragma unroll
    for (int k = 0; k < 4; k++)
        nv[k] = (v[k] - mu) * rs * gamma[c0 + k] + beta[c0 + k];
    uint2 pw = make_uint2(packbf(nv[0], nv[1]), packbf(nv[2], nv[3]));
    *(uint2*)&xn[(size_t)tok * 256 + (tid << 1)] = pw;
}

// ---------------------------------------------------------------------------
// Attention: one CTA per (window, head). bf16 in/out, fp32 math.
// ---------------------------------------------------------------------------
__global__ void __launch_bounds__(256) attn_k(
    const uint32_t* __restrict__ qkv, uint32_t* __restrict__ o)
{
    __shared__ uint32_t ks[64 * 36];
    __shared__ uint32_t vs[64 * 36];

    int tid  = threadIdx.x;
    int win  = blockIdx.x >> 3;
    int head = blockIdx.x & 7;
    const uint32_t* base = qkv + (size_t)win * 64 * 768 + head * 32;

    int row = tid >> 2;
    int q4  = tid & 3;
    int e0w = q4 << 3;           // word offset (8 words = 16 bf16)

    {
        const uint32_t* kp = base + 256 + row * 768 + e0w;
        const uint32_t* vp = base + 512 + row * 768 + e0w;
        *(uint4*)&ks[row * 36 + e0w]     = *(const uint4*)kp;
        *(uint4*)&ks[row * 36 + e0w + 4] = *(const uint4*)(kp + 4);
        *(uint4*)&vs[row * 36 + e0w]     = *(const uint4*)vp;
        *(uint4*)&vs[row * 36 + e0w + 4] = *(const uint4*)(vp + 4);
    }
    float qreg[16];
    {
        const float scl = 1.f / 4096.f;
        const uint32_t* qp = base + row * 768 + e0w;
#pragma unroll
        for (int j = 0; j < 8; j++) {
            uint32_t w = qp[j];
            qreg[2*j]   = bflo(w) * scl;
            qreg[2*j+1] = bfhi(w) * scl;
        }
    }
    __syncthreads();

    float p[64];
#pragma unroll
    for (int m = 0; m < 64; m++) {
        const uint32_t* kr = &ks[m * 36 + e0w];
        float acc = 0.f;
#pragma unroll
        for (int j = 0; j < 8; j++) {
            uint32_t w = kr[j];
            acc += qreg[2*j] * bflo(w) + qreg[2*j+1] * bfhi(w);
        }
        p[m] = acc;
    }
#pragma unroll
    for (int m = 0; m < 64; m++) {
        p[m] += __shfl_xor_sync(0xffffffffu, p[m], 1);
        p[m] += __shfl_xor_sync(0xffffffffu, p[m], 2);
    }
    float mx = -1e30f;
#pragma unroll
    for (int m = 0; m < 64; m++) mx = fmaxf(mx, p[m]);
    float sum = 0.f;
#pragma unroll
    for (int m = 0; m < 64; m++) { p[m] = expf(p[m] - mx); sum += p[m]; }
    float inv = 1.f / sum;

    float oa[16];
#pragma unroll
    for (int e = 0; e < 16; e++) oa[e] = 0.f;
#pragma unroll
    for (int m = 0; m < 64; m++) {
        float a = p[m] * inv;
        const uint32_t* vr = &vs[m * 36 + e0w];
#pragma unroll
        for (int j = 0; j < 8; j++) {
            uint32_t w = vr[j];
            oa[2*j]   += a * bflo(w);
            oa[2*j+1] += a * bfhi(w);
        }
    }
    uint32_t ow[8];
#pragma unroll
    for (int j = 0; j < 8; j++) ow[j] = packbf(oa[2*j], oa[2*j+1]);
    uint32_t* op = o + (size_t)win * 16384 + row * 256 + head * 32 + e0w;
    *(uint4*)op       = make_uint4(ow[0], ow[1], ow[2], ow[3]);
    *(uint4*)(op + 4) = make_uint4(ow[4], ow[5], ow[6], ow[7]);
}

// ---------------------------------------------------------------------------
// BF16 tensor-core GEMM. A: bf16 row-major [M][K] (word = k-pair).
// B: pre-packed k-pair words [K/2][N].
//   MODE 0: Cw = bf16(A@B + bias)
//   MODE 1: Cf += A@B + bias                     (fp32 residual in place)
//   MODE 2: Cw = bf16(gelu(A@B + bias))
//   MODE 3: out[x-layout] = Cf(residual) + A@B + bias
// CTA 128x128, BK=32 (16 kpair words), 256 thr = 8 warps (2Mx4N), warp 64x32.
// mma.m16n8k16, cp.async double buffer, conflict-free smem permutations.
// ---------------------------------------------------------------------------
#define AS_STRIDE 20
#define BS_STRIDE 136
#define AS_ELEMS (128 * AS_STRIDE)
#define BS_ELEMS (16 * BS_STRIDE)

__device__ __forceinline__ float gelu_exact(float v) {
    return 0.5f * v * (1.0f + erff(v * 0.70710678118654752440f));
}

__device__ __forceinline__ void mma_bf16(float* d, const uint32_t* a, const uint32_t* b) {
    asm volatile(
        "mma.sync.aligned.m16n8k16.row.col.f32.bf16.bf16.f32 "
        "{%0,%1,%2,%3}, {%4,%5,%6,%7}, {%8,%9}, {%0,%1,%2,%3};"
        : "+f"(d[0]), "+f"(d[1]), "+f"(d[2]), "+f"(d[3])
        : "r"(a[0]), "r"(a[1]), "r"(a[2]), "r"(a[3]), "r"(b[0]), "r"(b[1]));
}

__device__ __forceinline__ void cpa16(uint32_t dst, const void* src) {
    asm volatile("cp.async.cg.shared.global [%0], [%1], 16;" :: "r"(dst), "l"(src));
}
__device__ __forceinline__ void cp_commit() {
    asm volatile("cp.async.commit_group;");
}
template <int N_>
__device__ __forceinline__ void cp_wait() {
    asm volatile("cp.async.wait_group %0;" :: "n"(N_));
}

template <int MODE>
__global__ void __launch_bounds__(256, 2) bgemm_k(
    const uint32_t* __restrict__ A, const uint32_t* __restrict__ B,
    const float* __restrict__ bias, uint32_t* __restrict__ Cw,
    float* __restrict__ Cf, float* __restrict__ out, int M, int N, int K)
{
    __shared__ uint32_t As[2][AS_ELEMS];
    __shared__ uint32_t Bs[2][BS_ELEMS];

    int tid   = threadIdx.x;
    int lane  = tid & 31;
    int warp  = tid >> 5;
    int warpM = warp >> 2;   // 0..1 (64-row slab)
    int warpN = warp & 3;    // 0..3 (32-col slab)
    int row0  = blockIdx.y << 7;
    int col0  = blockIdx.x << 7;
    int Kw    = K >> 1;

    uint32_t as_base = (uint32_t)__cvta_generic_to_shared(&As[0][0]);
    uint32_t bs_base = (uint32_t)__cvta_generic_to_shared(&Bs[0][0]);

    // A loader: chunks tid, tid+256; chunk -> row=chunk>>2, word-quad=(chunk&3)*4
    int ar = tid >> 2, aw = (tid & 3) << 2;
    const uint32_t* Ag0 = A + (size_t)(row0 + ar) * Kw + aw;
    const uint32_t* Ag1 = Ag0 + (size_t)64 * Kw;
    uint32_t a_d0 = as_base + (uint32_t)(ar * AS_STRIDE + aw) * 4u;
    uint32_t a_d1 = a_d0 + 64 * AS_STRIDE * 4u;
    // B loader: chunks tid, tid+256; chunk -> kp=chunk>>5, ncol=(chunk&31)*4
    int bkp = tid >> 5, bn = (tid & 31) << 2;
    const uint32_t* Bg0 = B + (size_t)bkp * N + col0 + bn;
    const uint32_t* Bg1 = Bg0 + (size_t)8 * N;
    uint32_t b_d0 = bs_base + (uint32_t)(bkp * BS_STRIDE + bn) * 4u;
    uint32_t b_d1 = b_d0 + 8 * BS_STRIDE * 4u;

    int niter = K >> 5;   // BK=32 -> 16 kpair words per iter

    cpa16(a_d0, Ag0);
    cpa16(a_d1, Ag1);
    cpa16(b_d0, Bg0);
    cpa16(b_d1, Bg1);
    cp_commit();

    float acc[4][4][4];
#pragma unroll
    for (int mt = 0; mt < 4; mt++)
#pragma unroll
        for (int nt = 0; nt < 4; nt++)
#pragma unroll
            for (int e = 0; e < 4; e++) acc[mt][nt][e] = 0.f;

    int r = lane >> 2;   // 0..7
    int c = lane & 3;    // 0..3

    for (int it = 0; it < niter; it++) {
        int buf = it & 1;
        if (it + 1 < niter) {
            int nb = buf ^ 1;
            int k0w = (it + 1) << 4;
            uint32_t ao = (uint32_t)(nb * AS_ELEMS) * 4u;
            uint32_t bo = (uint32_t)(nb * BS_ELEMS) * 4u;
            cpa16(a_d0 + ao, Ag0 + k0w);
            cpa16(a_d1 + ao, Ag1 + k0w);
            cpa16(b_d0 + bo, Bg0 + (size_t)k0w * N);
            cpa16(b_d1 + bo, Bg1 + (size_t)k0w * N);
            cp_commit();
            cp_wait<1>();
        } else {
            cp_wait<0>();
        }
        __syncthreads();

        const uint32_t* as = &As[buf][warpM * 64 * AS_STRIDE];
        const uint32_t* bs = &Bs[buf][warpN * 32];

#pragma unroll
        for (int ks = 0; ks < 16; ks += 8) {
            uint32_t af[4][4];
#pragma unroll
            for (int mt = 0; mt < 4; mt++) {
                int rowa = mt * 16 + r;
                af[mt][0] = as[(rowa    ) * AS_STRIDE + ks + c    ];
                af[mt][1] = as[(rowa + 8) * AS_STRIDE + ks + c    ];
                af[mt][2] = as[(rowa    ) * AS_STRIDE + ks + c + 4];
                af[mt][3] = as[(rowa + 8) * AS_STRIDE + ks + c + 4];
            }
            uint32_t bf[4][2];
#pragma unroll
            for (int nt = 0; nt < 4; nt++) {
                bf[nt][0] = bs[(ks + c    ) * BS_STRIDE + nt * 8 + r];
                bf[nt][1] = bs[(ks + c + 4) * BS_STRIDE + nt * 8 + r];
            }
#pragma unroll
            for (int mt = 0; mt < 4; mt++)
#pragma unroll
                for (int nt = 0; nt < 4; nt++)
                    mma_bf16(acc[mt][nt], af[mt], bf[nt]);
        }
        __syncthreads();
    }

    // ---- epilogue ----
    int c2 = c << 1;
    int Nw = N >> 1;
#pragma unroll
    for (int nt = 0; nt < 4; nt++) {
        int gcol = col0 + warpN * 32 + nt * 8 + c2;
        float b0 = bias[gcol], b1 = bias[gcol + 1];
#pragma unroll
        for (int mt = 0; mt < 4; mt++) {
            int grow = row0 + warpM * 64 + mt * 16 + r;
#pragma unroll
            for (int half = 0; half < 2; half++) {
                int rr = grow + half * 8;
                float v0 = acc[mt][nt][half * 2 + 0] + b0;
                float v1 = acc[mt][nt][half * 2 + 1] + b1;
                if (MODE == 0) {
                    Cw[(size_t)rr * Nw + (gcol >> 1)] = packbf(v0, v1);
                } else if (MODE == 2) {
                    Cw[(size_t)rr * Nw + (gcol >> 1)] =
                        packbf(gelu_exact(v0), gelu_exact(v1));
                } else if (MODE == 1) {
                    float2 cur = *(float2*)&Cf[(size_t)rr * N + gcol];
                    cur.x += v0; cur.y += v1;
                    *(float2*)&Cf[(size_t)rr * N + gcol] = cur;
                } else { // MODE 3
                    float2 res = *(float2*)&Cf[(size_t)rr * N + gcol];
                    int b  = rr >> 14;
                    int n  = (rr >> 6) & 255;
                    int l  = rr & 63;
                    int hh = ((n >> 4) << 3) | (l >> 3);
                    int ww = ((n & 15) << 3) | (l & 7);
                    size_t sbase = ((size_t)(b * 512) << 14) + (size_t)(hh << 7) + ww;
                    out[sbase + ((size_t)gcol << 14)]       = v0 + res.x;
                    out[sbase + ((size_t)(gcol + 1) << 14)] = v1 + res.y;
                }
            }
        }
    }
}

// ---------------------------------------------------------------------------
// Launch sequence
// ---------------------------------------------------------------------------
extern "C" void kernel_launch(void* const* d_in, const int* in_sizes, int n_in,
                              void* d_out, int out_size)
{
    const float* x     = (const float*)d_in[0];
    const float* g1    = (const float*)d_in[1];
    const float* be1   = (const float*)d_in[2];
    const float* g2    = (const float*)d_in[3];
    const float* be2   = (const float*)d_in[4];
    const float* w_qkv = (const float*)d_in[5];
    const float* b_qkv = (const float*)d_in[6];
    const float* w_out = (const float*)d_in[7];
    const float* b_out = (const float*)d_in[8];
    const float* w1    = (const float*)d_in[9];
    const float* b1m   = (const float*)d_in[10];
    const float* w2    = (const float*)d_in[11];
    const float* b2m   = (const float*)d_in[12];
    float* out = (float*)d_out;

    float *t;
    uint32_t *xn, *qkv, *o, *hbuf, *wr;
    cudaGetSymbolAddress((void**)&t,    g_t);
    cudaGetSymbolAddress((void**)&xn,   g_xn);
    cudaGetSymbolAddress((void**)&qkv,  g_qkv);
    cudaGetSymbolAddress((void**)&o,    g_o);
    cudaGetSymbolAddress((void**)&hbuf, g_h);
    cudaGetSymbolAddress((void**)&wr,   g_w);

    // 0. pack weights to bf16 k-pair words
    wpack_k<<<WTOT / 256, 256>>>(w_qkv, w_out, w1, w2, wr);
    // 1. window partition + LN1
    ln1_part_k<<<TOKS, 128>>>(x, g1, be1, t, xn);
    // 2. qkv = xn @ w_qkv + b_qkv  (bf16 out)
    bgemm_k<0><<<dim3(12, 1024), 256>>>(xn, wr + WQKV_OFF, b_qkv, qkv, nullptr, nullptr, TOKS, 1536, 512);
    // 3. windowed attention (bf16 out)
    attn_k<<<(TOKS / 64) * 8, 256>>>(qkv, o);
    // 4. t += o @ w_out + b_out  (fp32 residual)
    bgemm_k<1><<<dim3(4, 1024), 256>>>(o, wr + WOUT_OFF, b_out, nullptr, t, nullptr, TOKS, 512, 512);
    // 5. LN2 (bf16 out)
    ln2_k<<<TOKS, 128>>>(t, g2, be2, xn);
    // 6. h = gelu(xn @ w1 + b1)  (bf16 out)
    bgemm_k<2><<<dim3(16, 1024), 256>>>(xn, wr + W1_OFF, b1m, hbuf, nullptr, nullptr, TOKS, 2048, 512);
    // 7. out[x-layout] = t + h @ w2 + b2  (fused un-partition)
    bgemm_k<3><<<dim3(4, 1024), 256>>>(hbuf, wr + W2_OFF, b2m, nullptr, t, out, TOKS, 512, 2048);
}

// round 5
// speedup vs baseline: 5.5360x; 1.2206x over previous
#include <cuda_runtime.h>
#include <math.h>
#include <stdint.h>

// ---------------------------------------------------------------------------
// B=8, C=512, H=W=128, WS=8, NH=8, hd=64, L=64, N=256 windows/batch
// TOKS = 8*256*64 = 131072
// Activations bf16 (packed 2/word); residual stream t stays fp32.
// ---------------------------------------------------------------------------
#define TOKS 131072

__device__ float    g_t  [(size_t)TOKS * 512];   // residual (fp32)
__device__ uint32_t g_xn [(size_t)TOKS * 256];   // LN out (bf16x2)
__device__ uint32_t g_qkv[(size_t)TOKS * 768];   // qkv (bf16x2)
__device__ uint32_t g_o  [(size_t)TOKS * 256];   // attn out (bf16x2)
__device__ uint32_t g_h  [(size_t)TOKS * 1024];  // mlp hidden (bf16x2)

// weights packed as k-pair bf16 words: word(kp,n) = (bf16 w[2kp][n], bf16 w[2kp+1][n])
#define WQKV_OFF 0
#define WOUT_OFF 393216
#define W1_OFF   524288
#define W2_OFF   1048576
#define WTOT     1572864
__device__ uint32_t g_w[WTOT];

__device__ __forceinline__ uint32_t packbf(float lo, float hi) {
    uint32_t u;
    asm("cvt.rn.bf16x2.f32 %0, %1, %2;" : "=r"(u) : "f"(hi), "f"(lo));
    return u;
}
__device__ __forceinline__ float bflo(uint32_t w) { return __uint_as_float(w << 16); }
__device__ __forceinline__ float bfhi(uint32_t w) { return __uint_as_float(w & 0xffff0000u); }

// ---------------------------------------------------------------------------
// Weight pack: fp32 [K][N] -> bf16-pair words [K/2][N]
// ---------------------------------------------------------------------------
__global__ void __launch_bounds__(256) wpack_k(
    const float* __restrict__ wqkv, const float* __restrict__ wout,
    const float* __restrict__ w1, const float* __restrict__ w2,
    uint32_t* __restrict__ dst)
{
    int idx = blockIdx.x * 256 + threadIdx.x;
    float lo, hi;
    if (idx < WOUT_OFF) {
        int kp = idx / 1536, n = idx - kp * 1536;
        lo = wqkv[(2 * kp) * 1536 + n]; hi = wqkv[(2 * kp + 1) * 1536 + n];
    } else if (idx < W1_OFF) {
        int l = idx - WOUT_OFF; int kp = l >> 9, n = l & 511;
        lo = wout[(2 * kp) * 512 + n]; hi = wout[(2 * kp + 1) * 512 + n];
    } else if (idx < W2_OFF) {
        int l = idx - W1_OFF; int kp = l >> 11, n = l & 2047;
        lo = w1[(2 * kp) * 2048 + n]; hi = w1[(2 * kp + 1) * 2048 + n];
    } else {
        int l = idx - W2_OFF; int kp = l >> 9, n = l & 511;
        lo = w2[(2 * kp) * 512 + n]; hi = w2[(2 * kp + 1) * 512 + n];
    }
    dst[idx] = packbf(lo, hi);
}

// ---------------------------------------------------------------------------
// Window partition + LayerNorm1: t fp32, xn bf16
// ---------------------------------------------------------------------------
__global__ void __launch_bounds__(128) ln1_part_k(
    const float* __restrict__ x, const float* __restrict__ gamma,
    const float* __restrict__ beta, float* __restrict__ t, uint32_t* __restrict__ xn)
{
    int tok = blockIdx.x;
    int tid = threadIdx.x;
    int b = tok >> 14;
    int n = (tok >> 6) & 255;
    int l = tok & 63;
    int h = ((n >> 4) << 3) | (l >> 3);
    int w = ((n & 15) << 3) | (l & 7);
    size_t base = ((size_t)b * 512) * 16384 + (size_t)(h << 7) + w;

    int c0 = tid << 2;
    float v[4];
    float s = 0.f, s2 = 0.f;
#pragma unroll
    for (int k = 0; k < 4; k++) {
        v[k] = x[base + ((size_t)(c0 + k) << 14)];
        s += v[k]; s2 += v[k] * v[k];
    }
#pragma unroll
    for (int off = 16; off; off >>= 1) {
        s  += __shfl_xor_sync(0xffffffffu, s,  off);
        s2 += __shfl_xor_sync(0xffffffffu, s2, off);
    }
    __shared__ float sh[8];
    int wid = tid >> 5, lane = tid & 31;
    if (lane == 0) { sh[wid] = s; sh[4 + wid] = s2; }
    __syncthreads();
    s  = sh[0] + sh[1] + sh[2] + sh[3];
    s2 = sh[4] + sh[5] + sh[6] + sh[7];
    float mu  = s  * (1.f / 512.f);
    float var = s2 * (1.f / 512.f) - mu * mu;
    float rs  = rsqrtf(var + 1e-5f);

    float nv[4];
#pragma unroll
    for (int k = 0; k < 4; k++)
        nv[k] = (v[k] - mu) * rs * gamma[c0 + k] + beta[c0 + k];

    *(float4*)&t[(size_t)tok * 512 + c0] = make_float4(v[0], v[1], v[2], v[3]);
    uint2 pw = make_uint2(packbf(nv[0], nv[1]), packbf(nv[2], nv[3]));
    *(uint2*)&xn[(size_t)tok * 256 + (tid << 1)] = pw;
}

// ---------------------------------------------------------------------------
// LayerNorm2: fp32 src (t) -> bf16 xn
// ---------------------------------------------------------------------------
__global__ void __launch_bounds__(128) ln2_k(
    const float* __restrict__ src, const float* __restrict__ gamma,
    const float* __restrict__ beta, uint32_t* __restrict__ xn)
{
    int tok = blockIdx.x;
    int tid = threadIdx.x;
    int c0 = tid << 2;
    float4 v4 = *(const float4*)&src[(size_t)tok * 512 + c0];
    float v[4] = {v4.x, v4.y, v4.z, v4.w};
    float s = v[0] + v[1] + v[2] + v[3];
    float s2 = v[0]*v[0] + v[1]*v[1] + v[2]*v[2] + v[3]*v[3];
#pragma unroll
    for (int off = 16; off; off >>= 1) {
        s  += __shfl_xor_sync(0xffffffffu, s,  off);
        s2 += __shfl_xor_sync(0xffffffffu, s2, off);
    }
    __shared__ float sh[8];
    int wid = tid >> 5, lane = tid & 31;
    if (lane == 0) { sh[wid] = s; sh[4 + wid] = s2; }
    __syncthreads();
    s  = sh[0] + sh[1] + sh[2] + sh[3];
    s2 = sh[4] + sh[5] + sh[6] + sh[7];
    float mu  = s  * (1.f / 512.f);
    float var = s2 * (1.f / 512.f) - mu * mu;
    float rs  = rsqrtf(var + 1e-5f);

    float nv[4];
#pragma unroll
    for (int k = 0; k < 4; k++)
        nv[k] = (v[k] - mu) * rs * gamma[c0 + k] + beta[c0 + k];
    uint2 pw = make_uint2(packbf(nv[0], nv[1]), packbf(nv[2], nv[3]));
    *(uint2*)&xn[(size_t)tok * 256 + (tid << 1)] = pw;
}

// ---------------------------------------------------------------------------
// Tensor-core attention: one CTA per (window, head), 4 warps.
// S = Q@K^T (mma m16n8k16), softmax in fragments, O = P@V via the
// C-frag->A-frag pack trick; V loaded with ldmatrix.trans.
// smem tiles 64 rows x 32 words, row stride 36 words (conflict-free ldmatrix).
// ---------------------------------------------------------------------------
__device__ __forceinline__ void ldsm4(uint32_t& r0, uint32_t& r1, uint32_t& r2,
                                      uint32_t& r3, uint32_t addr) {
    asm volatile("ldmatrix.sync.aligned.m8n8.x4.shared.b16 {%0,%1,%2,%3}, [%4];"
                 : "=r"(r0), "=r"(r1), "=r"(r2), "=r"(r3) : "r"(addr));
}
__device__ __forceinline__ void ldsm2(uint32_t& r0, uint32_t& r1, uint32_t addr) {
    asm volatile("ldmatrix.sync.aligned.m8n8.x2.shared.b16 {%0,%1}, [%2];"
                 : "=r"(r0), "=r"(r1) : "r"(addr));
}
__device__ __forceinline__ void ldsm2t(uint32_t& r0, uint32_t& r1, uint32_t addr) {
    asm volatile("ldmatrix.sync.aligned.m8n8.x2.trans.shared.b16 {%0,%1}, [%2];"
                 : "=r"(r0), "=r"(r1) : "r"(addr));
}
__device__ __forceinline__ void mma_bf16_a(float* d, uint32_t a0, uint32_t a1,
                                           uint32_t a2, uint32_t a3,
                                           uint32_t b0, uint32_t b1) {
    asm volatile(
        "mma.sync.aligned.m16n8k16.row.col.f32.bf16.bf16.f32 "
        "{%0,%1,%2,%3}, {%4,%5,%6,%7}, {%8,%9}, {%0,%1,%2,%3};"
        : "+f"(d[0]), "+f"(d[1]), "+f"(d[2]), "+f"(d[3])
        : "r"(a0), "r"(a1), "r"(a2), "r"(a3), "r"(b0), "r"(b1));
}

#define ATS 36   // smem row stride in words

__global__ void __launch_bounds__(128) attn_k(
    const uint32_t* __restrict__ qkv, uint32_t* __restrict__ o)
{
    __shared__ uint32_t sm[3 * 64 * ATS];
    uint32_t* qs = sm;
    uint32_t* ks = sm + 64 * ATS;
    uint32_t* vs = sm + 2 * 64 * ATS;

    int tid  = threadIdx.x;
    int lane = tid & 31;
    int warp = tid >> 5;
    int win  = blockIdx.x >> 3;
    int head = blockIdx.x & 7;

    // ---- stage Q, K, V tiles (64 rows x 32 words each) ----
    {
        int row = tid >> 1, half = tid & 1;
        size_t gbase = (size_t)(win * 64 + row) * 768 + head * 32 + half * 16;
        int sbase = row * ATS + half * 16;
#pragma unroll
        for (int sec = 0; sec < 3; sec++) {
            const uint4* src = (const uint4*)(qkv + gbase + sec * 256);
            uint4* dst = (uint4*)(sm + sec * 64 * ATS + sbase);
            dst[0] = src[0]; dst[1] = src[1]; dst[2] = src[2]; dst[3] = src[3];
        }
    }
    __syncthreads();

    uint32_t qs_u = (uint32_t)__cvta_generic_to_shared(qs);
    uint32_t ks_u = (uint32_t)__cvta_generic_to_shared(ks);
    uint32_t vs_u = (uint32_t)__cvta_generic_to_shared(vs);

    int r0  = warp << 4;
    int l8  = lane & 7;
    int l16 = lane & 15;

    // per-lane ldmatrix base addresses (word units *4 -> bytes)
    uint32_t qaddr = qs_u + (uint32_t)((r0 + l8 + (lane & 8)) * ATS + ((lane & 16) >> 2)) * 4u;
    uint32_t kaddr = ks_u + (uint32_t)((l16 & 7) * ATS + ((l16 & 8) >> 1)) * 4u;
    uint32_t vaddr = vs_u + (uint32_t)(((l16 & 7) + (l16 & 8)) * ATS) * 4u;

    // ---- S = Q @ K^T ----
    float sacc[8][4];
#pragma unroll
    for (int nt = 0; nt < 8; nt++)
#pragma unroll
        for (int e = 0; e < 4; e++) sacc[nt][e] = 0.f;

#pragma unroll
    for (int kt = 0; kt < 4; kt++) {
        uint32_t a0, a1, a2, a3;
        ldsm4(a0, a1, a2, a3, qaddr + (uint32_t)(kt * 8) * 4u);
#pragma unroll
        for (int nt = 0; nt < 8; nt++) {
            uint32_t b0, b1;
            ldsm2(b0, b1, kaddr + (uint32_t)(nt * 8 * ATS + kt * 8) * 4u);
            mma_bf16_a(sacc[nt], a0, a1, a2, a3, b0, b1);
        }
    }

    // ---- fragment softmax (rows r and r+8 per thread) ----
    const float scl = 1.f / 4096.f;
#pragma unroll
    for (int nt = 0; nt < 8; nt++)
#pragma unroll
        for (int e = 0; e < 4; e++) sacc[nt][e] *= scl;

    float m0 = -1e30f, m1 = -1e30f;
#pragma unroll
    for (int nt = 0; nt < 8; nt++) {
        m0 = fmaxf(m0, fmaxf(sacc[nt][0], sacc[nt][1]));
        m1 = fmaxf(m1, fmaxf(sacc[nt][2], sacc[nt][3]));
    }
    m0 = fmaxf(m0, __shfl_xor_sync(0xffffffffu, m0, 1));
    m0 = fmaxf(m0, __shfl_xor_sync(0xffffffffu, m0, 2));
    m1 = fmaxf(m1, __shfl_xor_sync(0xffffffffu, m1, 1));
    m1 = fmaxf(m1, __shfl_xor_sync(0xffffffffu, m1, 2));

    float sum0 = 0.f, sum1 = 0.f;
#pragma unroll
    for (int nt = 0; nt < 8; nt++) {
        sacc[nt][0] = __expf(sacc[nt][0] - m0); sum0 += sacc[nt][0];
        sacc[nt][1] = __expf(sacc[nt][1] - m0); sum0 += sacc[nt][1];
        sacc[nt][2] = __expf(sacc[nt][2] - m1); sum1 += sacc[nt][2];
        sacc[nt][3] = __expf(sacc[nt][3] - m1); sum1 += sacc[nt][3];
    }
    sum0 += __shfl_xor_sync(0xffffffffu, sum0, 1);
    sum0 += __shfl_xor_sync(0xffffffffu, sum0, 2);
    sum1 += __shfl_xor_sync(0xffffffffu, sum1, 1);
    sum1 += __shfl_xor_sync(0xffffffffu, sum1, 2);
    float inv0 = 1.f / sum0, inv1 = 1.f / sum1;

    // ---- pack P into A fragments (C-frag -> A-frag trick) ----
    uint32_t pw[4][4];
#pragma unroll
    for (int kt = 0; kt < 4; kt++) {
        pw[kt][0] = packbf(sacc[2*kt    ][0] * inv0, sacc[2*kt    ][1] * inv0);
        pw[kt][1] = packbf(sacc[2*kt    ][2] * inv1, sacc[2*kt    ][3] * inv1);
        pw[kt][2] = packbf(sacc[2*kt + 1][0] * inv0, sacc[2*kt + 1][1] * inv0);
        pw[kt][3] = packbf(sacc[2*kt + 1][2] * inv1, sacc[2*kt + 1][3] * inv1);
    }

    // ---- O = P @ V ----
    float oacc[8][4];
#pragma unroll
    for (int nt = 0; nt < 8; nt++)
#pragma unroll
        for (int e = 0; e < 4; e++) oacc[nt][e] = 0.f;

#pragma unroll
    for (int kt = 0; kt < 4; kt++) {
#pragma unroll
        for (int nt = 0; nt < 8; nt++) {
            uint32_t b0, b1;
            ldsm2t(b0, b1, vaddr + (uint32_t)(kt * 16 * ATS + nt * 4) * 4u);
            mma_bf16_a(oacc[nt], pw[kt][0], pw[kt][1], pw[kt][2], pw[kt][3], b0, b1);
        }
    }

    // ---- store O (bf16) ----
    int r  = lane >> 2;
    int cq = lane & 3;
    uint32_t* ob = o + (size_t)(win * 64 + r0 + r) * 256 + head * 32 + cq;
#pragma unroll
    for (int nt = 0; nt < 8; nt++) {
        ob[nt * 4]            = packbf(oacc[nt][0], oacc[nt][1]);
        ob[8 * 256 + nt * 4]  = packbf(oacc[nt][2], oacc[nt][3]);
    }
}

// ---------------------------------------------------------------------------
// BF16 tensor-core GEMM. A: bf16 row-major [M][K] (word = k-pair).
// B: pre-packed k-pair words [K/2][N].
//   MODE 0: Cw = bf16(A@B + bias)
//   MODE 1: Cf += A@B + bias                     (fp32 residual in place)
//   MODE 2: Cw = bf16(gelu(A@B + bias))
//   MODE 3: out[x-layout] = Cf(residual) + A@B + bias
// CTA 128x128, BK=32 (16 kpair words), 256 thr = 8 warps (2Mx4N), warp 64x32.
// ---------------------------------------------------------------------------
#define AS_STRIDE 20
#define BS_STRIDE 136
#define AS_ELEMS (128 * AS_STRIDE)
#define BS_ELEMS (16 * BS_STRIDE)

__device__ __forceinline__ float gelu_exact(float v) {
    return 0.5f * v * (1.0f + erff(v * 0.70710678118654752440f));
}

__device__ __forceinline__ void mma_bf16(float* d, const uint32_t* a, const uint32_t* b) {
    asm volatile(
        "mma.sync.aligned.m16n8k16.row.col.f32.bf16.bf16.f32 "
        "{%0,%1,%2,%3}, {%4,%5,%6,%7}, {%8,%9}, {%0,%1,%2,%3};"
        : "+f"(d[0]), "+f"(d[1]), "+f"(d[2]), "+f"(d[3])
        : "r"(a[0]), "r"(a[1]), "r"(a[2]), "r"(a[3]), "r"(b[0]), "r"(b[1]));
}

__device__ __forceinline__ void cpa16(uint32_t dst, const void* src) {
    asm volatile("cp.async.cg.shared.global [%0], [%1], 16;" :: "r"(dst), "l"(src));
}
__device__ __forceinline__ void cp_commit() {
    asm volatile("cp.async.commit_group;");
}
template <int N_>
__device__ __forceinline__ void cp_wait() {
    asm volatile("cp.async.wait_group %0;" :: "n"(N_));
}

template <int MODE>
__global__ void __launch_bounds__(256, 2) bgemm_k(
    const uint32_t* __restrict__ A, const uint32_t* __restrict__ B,
    const float* __restrict__ bias, uint32_t* __restrict__ Cw,
    float* __restrict__ Cf, float* __restrict__ out, int M, int N, int K)
{
    __shared__ uint32_t As[2][AS_ELEMS];
    __shared__ uint32_t Bs[2][BS_ELEMS];

    int tid   = threadIdx.x;
    int lane  = tid & 31;
    int warp  = tid >> 5;
    int warpM = warp >> 2;
    int warpN = warp & 3;
    int row0  = blockIdx.y << 7;
    int col0  = blockIdx.x << 7;
    int Kw    = K >> 1;

    uint32_t as_base = (uint32_t)__cvta_generic_to_shared(&As[0][0]);
    uint32_t bs_base = (uint32_t)__cvta_generic_to_shared(&Bs[0][0]);

    int ar = tid >> 2, aw = (tid & 3) << 2;
    const uint32_t* Ag0 = A + (size_t)(row0 + ar) * Kw + aw;
    const uint32_t* Ag1 = Ag0 + (size_t)64 * Kw;
    uint32_t a_d0 = as_base + (uint32_t)(ar * AS_STRIDE + aw) * 4u;
    uint32_t a_d1 = a_d0 + 64 * AS_STRIDE * 4u;
    int bkp = tid >> 5, bn = (tid & 31) << 2;
    const uint32_t* Bg0 = B + (size_t)bkp * N + col0 + bn;
    const uint32_t* Bg1 = Bg0 + (size_t)8 * N;
    uint32_t b_d0 = bs_base + (uint32_t)(bkp * BS_STRIDE + bn) * 4u;
    uint32_t b_d1 = b_d0 + 8 * BS_STRIDE * 4u;

    int niter = K >> 5;

    cpa16(a_d0, Ag0);
    cpa16(a_d1, Ag1);
    cpa16(b_d0, Bg0);
    cpa16(b_d1, Bg1);
    cp_commit();

    float acc[4][4][4];
#pragma unroll
    for (int mt = 0; mt < 4; mt++)
#pragma unroll
        for (int nt = 0; nt < 4; nt++)
#pragma unroll
            for (int e = 0; e < 4; e++) acc[mt][nt][e] = 0.f;

    int r = lane >> 2;
    int c = lane & 3;

    for (int it = 0; it < niter; it++) {
        int buf = it & 1;
        if (it + 1 < niter) {
            int nb = buf ^ 1;
            int k0w = (it + 1) << 4;
            uint32_t ao = (uint32_t)(nb * AS_ELEMS) * 4u;
            uint32_t bo = (uint32_t)(nb * BS_ELEMS) * 4u;
            cpa16(a_d0 + ao, Ag0 + k0w);
            cpa16(a_d1 + ao, Ag1 + k0w);
            cpa16(b_d0 + bo, Bg0 + (size_t)k0w * N);
            cpa16(b_d1 + bo, Bg1 + (size_t)k0w * N);
            cp_commit();
            cp_wait<1>();
        } else {
            cp_wait<0>();
        }
        __syncthreads();

        const uint32_t* as = &As[buf][warpM * 64 * AS_STRIDE];
        const uint32_t* bs = &Bs[buf][warpN * 32];

#pragma unroll
        for (int ks = 0; ks < 16; ks += 8) {
            uint32_t af[4][4];
#pragma unroll
            for (int mt = 0; mt < 4; mt++) {
                int rowa = mt * 16 + r;
                af[mt][0] = as[(rowa    ) * AS_STRIDE + ks + c    ];
                af[mt][1] = as[(rowa + 8) * AS_STRIDE + ks + c    ];
                af[mt][2] = as[(rowa    ) * AS_STRIDE + ks + c + 4];
                af[mt][3] = as[(rowa + 8) * AS_STRIDE + ks + c + 4];
            }
            uint32_t bf[4][2];
#pragma unroll
            for (int nt = 0; nt < 4; nt++) {
                bf[nt][0] = bs[(ks + c    ) * BS_STRIDE + nt * 8 + r];
                bf[nt][1] = bs[(ks + c + 4) * BS_STRIDE + nt * 8 + r];
            }
#pragma unroll
            for (int mt = 0; mt < 4; mt++)
#pragma unroll
                for (int nt = 0; nt < 4; nt++)
                    mma_bf16(acc[mt][nt], af[mt], bf[nt]);
        }
        __syncthreads();
    }

    // ---- epilogue ----
    int c2 = c << 1;
    int Nw = N >> 1;
#pragma unroll
    for (int nt = 0; nt < 4; nt++) {
        int gcol = col0 + warpN * 32 + nt * 8 + c2;
        float b0 = bias[gcol], b1 = bias[gcol + 1];
#pragma unroll
        for (int mt = 0; mt < 4; mt++) {
            int grow = row0 + warpM * 64 + mt * 16 + r;
#pragma unroll
            for (int half = 0; half < 2; half++) {
                int rr = grow + half * 8;
                float v0 = acc[mt][nt][half * 2 + 0] + b0;
                float v1 = acc[mt][nt][half * 2 + 1] + b1;
                if (MODE == 0) {
                    Cw[(size_t)rr * Nw + (gcol >> 1)] = packbf(v0, v1);
                } else if (MODE == 2) {
                    Cw[(size_t)rr * Nw + (gcol >> 1)] =
                        packbf(gelu_exact(v0), gelu_exact(v1));
                } else if (MODE == 1) {
                    float2 cur = *(float2*)&Cf[(size_t)rr * N + gcol];
                    cur.x += v0; cur.y += v1;
                    *(float2*)&Cf[(size_t)rr * N + gcol] = cur;
                } else { // MODE 3
                    float2 res = *(float2*)&Cf[(size_t)rr * N + gcol];
                    int b  = rr >> 14;
                    int n  = (rr >> 6) & 255;
                    int l  = rr & 63;
                    int hh = ((n >> 4) << 3) | (l >> 3);
                    int ww = ((n & 15) << 3) | (l & 7);
                    size_t sbase = ((size_t)(b * 512) << 14) + (size_t)(hh << 7) + ww;
                    out[sbase + ((size_t)gcol << 14)]       = v0 + res.x;
                    out[sbase + ((size_t)(gcol + 1) << 14)] = v1 + res.y;
                }
            }
        }
    }
}

// ---------------------------------------------------------------------------
// Launch sequence
// ---------------------------------------------------------------------------
extern "C" void kernel_launch(void* const* d_in, const int* in_sizes, int n_in,
                              void* d_out, int out_size)
{
    const float* x     = (const float*)d_in[0];
    const float* g1    = (const float*)d_in[1];
    const float* be1   = (const float*)d_in[2];
    const float* g2    = (const float*)d_in[3];
    const float* be2   = (const float*)d_in[4];
    const float* w_qkv = (const float*)d_in[5];
    const float* b_qkv = (const float*)d_in[6];
    const float* w_out = (const float*)d_in[7];
    const float* b_out = (const float*)d_in[8];
    const float* w1    = (const float*)d_in[9];
    const float* b1m   = (const float*)d_in[10];
    const float* w2    = (const float*)d_in[11];
    const float* b2m   = (const float*)d_in[12];
    float* out = (float*)d_out;

    float *t;
    uint32_t *xn, *qkv, *o, *hbuf, *wr;
    cudaGetSymbolAddress((void**)&t,    g_t);
    cudaGetSymbolAddress((void**)&xn,   g_xn);
    cudaGetSymbolAddress((void**)&qkv,  g_qkv);
    cudaGetSymbolAddress((void**)&o,    g_o);
    cudaGetSymbolAddress((void**)&hbuf, g_h);
    cudaGetSymbolAddress((void**)&wr,   g_w);

    // 0. pack weights to bf16 k-pair words
    wpack_k<<<WTOT / 256, 256>>>(w_qkv, w_out, w1, w2, wr);
    // 1. window partition + LN1
    ln1_part_k<<<TOKS, 128>>>(x, g1, be1, t, xn);
    // 2. qkv = xn @ w_qkv + b_qkv  (bf16 out)
    bgemm_k<0><<<dim3(12, 1024), 256>>>(xn, wr + WQKV_OFF, b_qkv, qkv, nullptr, nullptr, TOKS, 1536, 512);
    // 3. windowed attention (tensor cores)
    attn_k<<<(TOKS / 64) * 8, 128>>>(qkv, o);
    // 4. t += o @ w_out + b_out  (fp32 residual)
    bgemm_k<1><<<dim3(4, 1024), 256>>>(o, wr + WOUT_OFF, b_out, nullptr, t, nullptr, TOKS, 512, 512);
    // 5. LN2 (bf16 out)
    ln2_k<<<TOKS, 128>>>(t, g2, be2, xn);
    // 6. h = gelu(xn @ w1 + b1)  (bf16 out)
    bgemm_k<2><<<dim3(16, 1024), 256>>>(xn, wr + W1_OFF, b1m, hbuf, nullptr, nullptr, TOKS, 2048, 512);
    // 7. out[x-layout] = t + h @ w2 + b2  (fused un-partition)
    bgemm_k<3><<<dim3(4, 1024), 256>>>(hbuf, wr + W2_OFF, b2m, nullptr, t, out, TOKS, 512, 2048);
}

// round 8
// speedup vs baseline: 5.9572x; 1.0761x over previous
#include <cuda_runtime.h>
#include <math.h>
#include <stdint.h>

// ---------------------------------------------------------------------------
// B=8, C=512, H=W=128, WS=8, NH=8, hd=64, L=64, N=256 windows/batch
// TOKS = 8*256*64 = 131072
// Activations bf16 (packed 2/word); residual stream t stays fp32.
// ---------------------------------------------------------------------------
#define TOKS 131072

__device__ float    g_t  [(size_t)TOKS * 512];   // residual (fp32)
__device__ uint32_t g_xn [(size_t)TOKS * 256];   // LN out (bf16x2)
__device__ uint32_t g_qkv[(size_t)TOKS * 768];   // qkv (bf16x2)
__device__ uint32_t g_o  [(size_t)TOKS * 256];   // attn out (bf16x2)
__device__ uint32_t g_h  [(size_t)TOKS * 1024];  // mlp hidden (bf16x2)

// weights packed as k-pair bf16 words: word(kp,n) = (bf16 w[2kp][n], bf16 w[2kp+1][n])
#define WQKV_OFF 0
#define WOUT_OFF 393216
#define W1_OFF   524288
#define W2_OFF   1048576
#define WTOT     1572864
__device__ uint32_t g_w[WTOT];

__device__ __forceinline__ uint32_t packbf(float lo, float hi) {
    uint32_t u;
    asm("cvt.rn.bf16x2.f32 %0, %1, %2;" : "=r"(u) : "f"(hi), "f"(lo));
    return u;
}

// ---------------------------------------------------------------------------
// Weight pack: fp32 [K][N] -> bf16-pair words [K/2][N]
// ---------------------------------------------------------------------------
__global__ void __launch_bounds__(256) wpack_k(
    const float* __restrict__ wqkv, const float* __restrict__ wout,
    const float* __restrict__ w1, const float* __restrict__ w2,
    uint32_t* __restrict__ dst)
{
    int idx = blockIdx.x * 256 + threadIdx.x;
    float lo, hi;
    if (idx < WOUT_OFF) {
        int kp = idx / 1536, n = idx - kp * 1536;
        lo = wqkv[(2 * kp) * 1536 + n]; hi = wqkv[(2 * kp + 1) * 1536 + n];
    } else if (idx < W1_OFF) {
        int l = idx - WOUT_OFF; int kp = l >> 9, n = l & 511;
        lo = wout[(2 * kp) * 512 + n]; hi = wout[(2 * kp + 1) * 512 + n];
    } else if (idx < W2_OFF) {
        int l = idx - W1_OFF; int kp = l >> 11, n = l & 2047;
        lo = w1[(2 * kp) * 2048 + n]; hi = w1[(2 * kp + 1) * 2048 + n];
    } else {
        int l = idx - W2_OFF; int kp = l >> 9, n = l & 511;
        lo = w2[(2 * kp) * 512 + n]; hi = w2[(2 * kp + 1) * 512 + n];
    }
    dst[idx] = packbf(lo, hi);
}

// ---------------------------------------------------------------------------
// Window partition + LayerNorm1, coalesced.
// One CTA per 8-token window row (same b,n,h; w = w0..w0+7).
// Thread = channel pair (c0 = 2*tid); 512 channels total -> mean = sum/512.
// ---------------------------------------------------------------------------
__global__ void __launch_bounds__(256) ln1_part_k(
    const float* __restrict__ x, const float* __restrict__ gamma,
    const float* __restrict__ beta, float* __restrict__ t, uint32_t* __restrict__ xn)
{
    int tid  = threadIdx.x;
    int tok0 = blockIdx.x << 3;
    int b  = tok0 >> 14;
    int n  = (tok0 >> 6) & 255;
    int l0 = tok0 & 63;
    int h  = ((n >> 4) << 3) | (l0 >> 3);
    int w0 = (n & 15) << 3;
    int c0 = tid << 1;

    size_t base0 = ((size_t)(b * 512 + c0)) * 16384 + (size_t)(h << 7) + w0;

    float va[8], vb[8];
    {
        float4 p0 = *(const float4*)(x + base0);
        float4 p1 = *(const float4*)(x + base0 + 4);
        float4 p2 = *(const float4*)(x + base0 + 16384);
        float4 p3 = *(const float4*)(x + base0 + 16388);
        va[0]=p0.x; va[1]=p0.y; va[2]=p0.z; va[3]=p0.w;
        va[4]=p1.x; va[5]=p1.y; va[6]=p1.z; va[7]=p1.w;
        vb[0]=p2.x; vb[1]=p2.y; vb[2]=p2.z; vb[3]=p2.w;
        vb[4]=p3.x; vb[5]=p3.y; vb[6]=p3.z; vb[7]=p3.w;
    }

    float s[8], s2[8];
#pragma unroll
    for (int ww = 0; ww < 8; ww++) {
        s[ww]  = va[ww] + vb[ww];
        s2[ww] = va[ww] * va[ww] + vb[ww] * vb[ww];
    }
#pragma unroll
    for (int off = 16; off; off >>= 1) {
#pragma unroll
        for (int ww = 0; ww < 8; ww++) {
            s[ww]  += __shfl_xor_sync(0xffffffffu, s[ww],  off);
            s2[ww] += __shfl_xor_sync(0xffffffffu, s2[ww], off);
        }
    }

    __shared__ float red[8][16];
    __shared__ float mr[16];
    int warp = tid >> 5, lane = tid & 31;
    if (lane == 0) {
#pragma unroll
        for (int ww = 0; ww < 8; ww++) {
            red[warp][ww]     = s[ww];
            red[warp][8 + ww] = s2[ww];
        }
    }
    __syncthreads();
    if (tid < 8) {
        float ts = 0.f, ts2 = 0.f;
#pragma unroll
        for (int wp = 0; wp < 8; wp++) {
            ts  += red[wp][tid];
            ts2 += red[wp][8 + tid];
        }
        float mu  = ts * (1.f / 512.f);
        float var = ts2 * (1.f / 512.f) - mu * mu;
        mr[tid]     = mu;
        mr[8 + tid] = rsqrtf(var + 1e-5f);
    }
    __syncthreads();

    float ga = gamma[c0], gb = gamma[c0 + 1];
    float ba = beta[c0],  bb = beta[c0 + 1];
#pragma unroll
    for (int ww = 0; ww < 8; ww++) {
        int tok = tok0 + ww;
        float mu = mr[ww], rs = mr[8 + ww];
        float n0 = (va[ww] - mu) * rs * ga + ba;
        float n1 = (vb[ww] - mu) * rs * gb + bb;
        *(float2*)&t[(size_t)tok * 512 + c0] = make_float2(va[ww], vb[ww]);
        xn[(size_t)tok * 256 + tid] = packbf(n0, n1);
    }
}

// ---------------------------------------------------------------------------
// LayerNorm2: fp32 src (t) -> bf16 xn
// ---------------------------------------------------------------------------
__global__ void __launch_bounds__(128) ln2_k(
    const float* __restrict__ src, const float* __restrict__ gamma,
    const float* __restrict__ beta, uint32_t* __restrict__ xn)
{
    int tok = blockIdx.x;
    int tid = threadIdx.x;
    int c0 = tid << 2;
    float4 v4 = *(const float4*)&src[(size_t)tok * 512 + c0];
    float v[4] = {v4.x, v4.y, v4.z, v4.w};
    float s = v[0] + v[1] + v[2] + v[3];
    float s2 = v[0]*v[0] + v[1]*v[1] + v[2]*v[2] + v[3]*v[3];
#pragma unroll
    for (int off = 16; off; off >>= 1) {
        s  += __shfl_xor_sync(0xffffffffu, s,  off);
        s2 += __shfl_xor_sync(0xffffffffu, s2, off);
    }
    __shared__ float sh[8];
    int wid = tid >> 5, lane = tid & 31;
    if (lane == 0) { sh[wid] = s; sh[4 + wid] = s2; }
    __syncthreads();
    s  = sh[0] + sh[1] + sh[2] + sh[3];
    s2 = sh[4] + sh[5] + sh[6] + sh[7];
    float mu  = s  * (1.f / 512.f);
    float var = s2 * (1.f / 512.f) - mu * mu;
    float rs  = rsqrtf(var + 1e-5f);

    float nv[4];
#pragma unroll
    for (int k = 0; k < 4; k++)
        nv[k] = (v[k] - mu) * rs * gamma[c0 + k] + beta[c0 + k];
    uint2 pw = make_uint2(packbf(nv[0], nv[1]), packbf(nv[2], nv[3]));
    *(uint2*)&xn[(size_t)tok * 256 + (tid << 1)] = pw;
}

// ---------------------------------------------------------------------------
// Tensor-core attention (mma.sync)
// ---------------------------------------------------------------------------
__device__ __forceinline__ void ldsm4(uint32_t& r0, uint32_t& r1, uint32_t& r2,
                                      uint32_t& r3, uint32_t addr) {
    asm volatile("ldmatrix.sync.aligned.m8n8.x4.shared.b16 {%0,%1,%2,%3}, [%4];"
                 : "=r"(r0), "=r"(r1), "=r"(r2), "=r"(r3) : "r"(addr));
}
__device__ __forceinline__ void ldsm2(uint32_t& r0, uint32_t& r1, uint32_t addr) {
    asm volatile("ldmatrix.sync.aligned.m8n8.x2.shared.b16 {%0,%1}, [%2];"
                 : "=r"(r0), "=r"(r1) : "r"(addr));
}
__device__ __forceinline__ void ldsm2t(uint32_t& r0, uint32_t& r1, uint32_t addr) {
    asm volatile("ldmatrix.sync.aligned.m8n8.x2.trans.shared.b16 {%0,%1}, [%2];"
                 : "=r"(r0), "=r"(r1) : "r"(addr));
}
__device__ __forceinline__ void mma_bf16_a(float* d, uint32_t a0, uint32_t a1,
                                           uint32_t a2, uint32_t a3,
                                           uint32_t b0, uint32_t b1) {
    asm volatile(
        "mma.sync.aligned.m16n8k16.row.col.f32.bf16.bf16.f32 "
        "{%0,%1,%2,%3}, {%4,%5,%6,%7}, {%8,%9}, {%0,%1,%2,%3};"
        : "+f"(d[0]), "+f"(d[1]), "+f"(d[2]), "+f"(d[3])
        : "r"(a0), "r"(a1), "r"(a2), "r"(a3), "r"(b0), "r"(b1));
}

#define ATS 36

__global__ void __launch_bounds__(128) attn_k(
    const uint32_t* __restrict__ qkv, uint32_t* __restrict__ o)
{
    __shared__ uint32_t sm[3 * 64 * ATS];
    uint32_t* qs = sm;
    uint32_t* ks = sm + 64 * ATS;
    uint32_t* vs = sm + 2 * 64 * ATS;

    int tid  = threadIdx.x;
    int lane = tid & 31;
    int warp = tid >> 5;
    int win  = blockIdx.x >> 3;
    int head = blockIdx.x & 7;

    {
        int row = tid >> 1, half = tid & 1;
        size_t gbase = (size_t)(win * 64 + row) * 768 + head * 32 + half * 16;
        int sbase = row * ATS + half * 16;
#pragma unroll
        for (int sec = 0; sec < 3; sec++) {
            const uint4* src = (const uint4*)(qkv + gbase + sec * 256);
            uint4* dst = (uint4*)(sm + sec * 64 * ATS + sbase);
            dst[0] = src[0]; dst[1] = src[1]; dst[2] = src[2]; dst[3] = src[3];
        }
    }
    __syncthreads();

    uint32_t qs_u = (uint32_t)__cvta_generic_to_shared(qs);
    uint32_t ks_u = (uint32_t)__cvta_generic_to_shared(ks);
    uint32_t vs_u = (uint32_t)__cvta_generic_to_shared(vs);

    int r0  = warp << 4;
    int l8  = lane & 7;
    int l16 = lane & 15;

    uint32_t qaddr = qs_u + (uint32_t)((r0 + l8 + (lane & 8)) * ATS + ((lane & 16) >> 2)) * 4u;
    uint32_t kaddr = ks_u + (uint32_t)((l16 & 7) * ATS + ((l16 & 8) >> 1)) * 4u;
    uint32_t vaddr = vs_u + (uint32_t)(((l16 & 7) + (l16 & 8)) * ATS) * 4u;

    float sacc[8][4];
#pragma unroll
    for (int nt = 0; nt < 8; nt++)
#pragma unroll
        for (int e = 0; e < 4; e++) sacc[nt][e] = 0.f;

#pragma unroll
    for (int kt = 0; kt < 4; kt++) {
        uint32_t a0, a1, a2, a3;
        ldsm4(a0, a1, a2, a3, qaddr + (uint32_t)(kt * 8) * 4u);
#pragma unroll
        for (int nt = 0; nt < 8; nt++) {
            uint32_t b0, b1;
            ldsm2(b0, b1, kaddr + (uint32_t)(nt * 8 * ATS + kt * 8) * 4u);
            mma_bf16_a(sacc[nt], a0, a1, a2, a3, b0, b1);
        }
    }

    const float scl = 1.f / 4096.f;
#pragma unroll
    for (int nt = 0; nt < 8; nt++)
#pragma unroll
        for (int e = 0; e < 4; e++) sacc[nt][e] *= scl;

    float m0 = -1e30f, m1 = -1e30f;
#pragma unroll
    for (int nt = 0; nt < 8; nt++) {
        m0 = fmaxf(m0, fmaxf(sacc[nt][0], sacc[nt][1]));
        m1 = fmaxf(m1, fmaxf(sacc[nt][2], sacc[nt][3]));
    }
    m0 = fmaxf(m0, __shfl_xor_sync(0xffffffffu, m0, 1));
    m0 = fmaxf(m0, __shfl_xor_sync(0xffffffffu, m0, 2));
    m1 = fmaxf(m1, __shfl_xor_sync(0xffffffffu, m1, 1));
    m1 = fmaxf(m1, __shfl_xor_sync(0xffffffffu, m1, 2));

    float sum0 = 0.f, sum1 = 0.f;
#pragma unroll
    for (int nt = 0; nt < 8; nt++) {
        sacc[nt][0] = __expf(sacc[nt][0] - m0); sum0 += sacc[nt][0];
        sacc[nt][1] = __expf(sacc[nt][1] - m0); sum0 += sacc[nt][1];
        sacc[nt][2] = __expf(sacc[nt][2] - m1); sum1 += sacc[nt][2];
        sacc[nt][3] = __expf(sacc[nt][3] - m1); sum1 += sacc[nt][3];
    }
    sum0 += __shfl_xor_sync(0xffffffffu, sum0, 1);
    sum0 += __shfl_xor_sync(0xffffffffu, sum0, 2);
    sum1 += __shfl_xor_sync(0xffffffffu, sum1, 1);
    sum1 += __shfl_xor_sync(0xffffffffu, sum1, 2);
    float inv0 = 1.f / sum0, inv1 = 1.f / sum1;

    uint32_t pw[4][4];
#pragma unroll
    for (int kt = 0; kt < 4; kt++) {
        pw[kt][0] = packbf(sacc[2*kt    ][0] * inv0, sacc[2*kt    ][1] * inv0);
        pw[kt][1] = packbf(sacc[2*kt    ][2] * inv1, sacc[2*kt    ][3] * inv1);
        pw[kt][2] = packbf(sacc[2*kt + 1][0] * inv0, sacc[2*kt + 1][1] * inv0);
        pw[kt][3] = packbf(sacc[2*kt + 1][2] * inv1, sacc[2*kt + 1][3] * inv1);
    }

    float oacc[8][4];
#pragma unroll
    for (int nt = 0; nt < 8; nt++)
#pragma unroll
        for (int e = 0; e < 4; e++) oacc[nt][e] = 0.f;

#pragma unroll
    for (int kt = 0; kt < 4; kt++) {
#pragma unroll
        for (int nt = 0; nt < 8; nt++) {
            uint32_t b0, b1;
            ldsm2t(b0, b1, vaddr + (uint32_t)(kt * 16 * ATS + nt * 4) * 4u);
            mma_bf16_a(oacc[nt], pw[kt][0], pw[kt][1], pw[kt][2], pw[kt][3], b0, b1);
        }
    }

    int r  = lane >> 2;
    int cq = lane & 3;
    uint32_t* ob = o + (size_t)(win * 64 + r0 + r) * 256 + head * 32 + cq;
#pragma unroll
    for (int nt = 0; nt < 8; nt++) {
        ob[nt * 4]            = packbf(oacc[nt][0], oacc[nt][1]);
        ob[8 * 256 + nt * 4]  = packbf(oacc[nt][2], oacc[nt][3]);
    }
}

// ---------------------------------------------------------------------------
// BF16 tensor-core GEMM, 3-stage cp.async pipeline, 1 sync per K-iter.
//   MODE 0: Cw = bf16(A@B + bias)
//   MODE 1: Cf += A@B + bias                     (fp32 residual in place)
//   MODE 2: Cw = bf16(gelu(A@B + bias))
//   MODE 3: out[x-layout] = Cf(residual) + A@B + bias
// CTA 128x128, BK=32 (16 kpair words), 256 thr = 8 warps (2Mx4N), warp 64x32.
// ---------------------------------------------------------------------------
#define AS_STRIDE 20
#define BS_STRIDE 136
#define AS_ELEMS (128 * AS_STRIDE)
#define BS_ELEMS (16 * BS_STRIDE)
#define BG_SMEM ((3 * AS_ELEMS + 3 * BS_ELEMS) * 4)

__device__ __forceinline__ float gelu_exact(float v) {
    return 0.5f * v * (1.0f + erff(v * 0.70710678118654752440f));
}

__device__ __forceinline__ void mma_bf16(float* d, const uint32_t* a, const uint32_t* b) {
    asm volatile(
        "mma.sync.aligned.m16n8k16.row.col.f32.bf16.bf16.f32 "
        "{%0,%1,%2,%3}, {%4,%5,%6,%7}, {%8,%9}, {%0,%1,%2,%3};"
        : "+f"(d[0]), "+f"(d[1]), "+f"(d[2]), "+f"(d[3])
        : "r"(a[0]), "r"(a[1]), "r"(a[2]), "r"(a[3]), "r"(b[0]), "r"(b[1]));
}

__device__ __forceinline__ void cpa16(uint32_t dst, const void* src) {
    asm volatile("cp.async.cg.shared.global [%0], [%1], 16;" :: "r"(dst), "l"(src));
}
__device__ __forceinline__ void cp_commit() {
    asm volatile("cp.async.commit_group;");
}
template <int N_>
__device__ __forceinline__ void cp_wait() {
    asm volatile("cp.async.wait_group %0;" :: "n"(N_));
}

template <int MODE>
__global__ void __launch_bounds__(256, 2) bgemm_k(
    const uint32_t* __restrict__ A, const uint32_t* __restrict__ B,
    const float* __restrict__ bias, uint32_t* __restrict__ Cw,
    float* __restrict__ Cf, float* __restrict__ out, int M, int N, int K)
{
    extern __shared__ uint32_t sm3[];
    uint32_t* Asm = sm3;                  // 3 stages of A
    uint32_t* Bsm = sm3 + 3 * AS_ELEMS;   // 3 stages of B

    int tid   = threadIdx.x;
    int lane  = tid & 31;
    int warp  = tid >> 5;
    int warpM = warp >> 2;
    int warpN = warp & 3;
    int row0  = blockIdx.y << 7;
    int col0  = blockIdx.x << 7;
    int Kw    = K >> 1;

    uint32_t as_base = (uint32_t)__cvta_generic_to_shared(Asm);
    uint32_t bs_base = (uint32_t)__cvta_generic_to_shared(Bsm);

    int ar = tid >> 2, aw = (tid & 3) << 2;
    const uint32_t* Ag0 = A + (size_t)(row0 + ar) * Kw + aw;
    const uint32_t* Ag1 = Ag0 + (size_t)64 * Kw;
    uint32_t a_d0 = as_base + (uint32_t)(ar * AS_STRIDE + aw) * 4u;
    uint32_t a_d1 = a_d0 + 64 * AS_STRIDE * 4u;
    int bkp = tid >> 5, bn = (tid & 31) << 2;
    const uint32_t* Bg0 = B + (size_t)bkp * N + col0 + bn;
    const uint32_t* Bg1 = Bg0 + (size_t)8 * N;
    uint32_t b_d0 = bs_base + (uint32_t)(bkp * BS_STRIDE + bn) * 4u;
    uint32_t b_d1 = b_d0 + 8 * BS_STRIDE * 4u;

    int niter = K >> 5;

    // prologue: prefetch iters 0 and 1 into stages 0 and 1
#pragma unroll
    for (int p = 0; p < 2; p++) {
        uint32_t ao = (uint32_t)(p * AS_ELEMS) * 4u;
        uint32_t bo = (uint32_t)(p * BS_ELEMS) * 4u;
        int k0w = p << 4;
        cpa16(a_d0 + ao, Ag0 + k0w);
        cpa16(a_d1 + ao, Ag1 + k0w);
        cpa16(b_d0 + bo, Bg0 + (size_t)k0w * N);
        cpa16(b_d1 + bo, Bg1 + (size_t)k0w * N);
        cp_commit();
    }

    float acc[4][4][4];
#pragma unroll
    for (int mt = 0; mt < 4; mt++)
#pragma unroll
        for (int nt = 0; nt < 4; nt++)
#pragma unroll
            for (int e = 0; e < 4; e++) acc[mt][nt][e] = 0.f;

    int r = lane >> 2;
    int c = lane & 3;

    int stage = 0, nstage = 2;
    for (int it = 0; it < niter; it++) {
        if (it + 1 < niter) cp_wait<1>();
        else                cp_wait<0>();
        __syncthreads();

        // prefetch it+2 into nstage (stage of it-1, finished before this sync)
        if (it + 2 < niter) {
            uint32_t ao = (uint32_t)(nstage * AS_ELEMS) * 4u;
            uint32_t bo = (uint32_t)(nstage * BS_ELEMS) * 4u;
            int k0w = (it + 2) << 4;
            cpa16(a_d0 + ao, Ag0 + k0w);
            cpa16(a_d1 + ao, Ag1 + k0w);
            cpa16(b_d0 + bo, Bg0 + (size_t)k0w * N);
            cpa16(b_d1 + bo, Bg1 + (size_t)k0w * N);
            cp_commit();
        }

        const uint32_t* as = &Asm[stage * AS_ELEMS + warpM * 64 * AS_STRIDE];
        const uint32_t* bs = &Bsm[stage * BS_ELEMS + warpN * 32];

#pragma unroll
        for (int ks = 0; ks < 16; ks += 8) {
            uint32_t af[4][4];
#pragma unroll
            for (int mt = 0; mt < 4; mt++) {
                int rowa = mt * 16 + r;
                af[mt][0] = as[(rowa    ) * AS_STRIDE + ks + c    ];
                af[mt][1] = as[(rowa + 8) * AS_STRIDE + ks + c    ];
                af[mt][2] = as[(rowa    ) * AS_STRIDE + ks + c + 4];
                af[mt][3] = as[(rowa + 8) * AS_STRIDE + ks + c + 4];
            }
            uint32_t bf[4][2];
#pragma unroll
            for (int nt = 0; nt < 4; nt++) {
                bf[nt][0] = bs[(ks + c    ) * BS_STRIDE + nt * 8 + r];
                bf[nt][1] = bs[(ks + c + 4) * BS_STRIDE + nt * 8 + r];
            }
#pragma unroll
            for (int mt = 0; mt < 4; mt++)
#pragma unroll
                for (int nt = 0; nt < 4; nt++)
                    mma_bf16(acc[mt][nt], af[mt], bf[nt]);
        }

        stage = (stage == 2) ? 0 : stage + 1;
        nstage = (nstage == 2) ? 0 : nstage + 1;
    }

    // ---- epilogue ----
    int c2 = c << 1;
    int Nw = N >> 1;
#pragma unroll
    for (int nt = 0; nt < 4; nt++) {
        int gcol = col0 + warpN * 32 + nt * 8 + c2;
        float b0 = bias[gcol], b1 = bias[gcol + 1];
#pragma unroll
        for (int mt = 0; mt < 4; mt++) {
            int grow = row0 + warpM * 64 + mt * 16 + r;
#pragma unroll
            for (int half = 0; half < 2; half++) {
                int rr = grow + half * 8;
                float v0 = acc[mt][nt][half * 2 + 0] + b0;
                float v1 = acc[mt][nt][half * 2 + 1] + b1;
                if (MODE == 0) {
                    Cw[(size_t)rr * Nw + (gcol >> 1)] = packbf(v0, v1);
                } else if (MODE == 2) {
                    Cw[(size_t)rr * Nw + (gcol >> 1)] =
                        packbf(gelu_exact(v0), gelu_exact(v1));
                } else if (MODE == 1) {
                    float2 cur = *(float2*)&Cf[(size_t)rr * N + gcol];
                    cur.x += v0; cur.y += v1;
                    *(float2*)&Cf[(size_t)rr * N + gcol] = cur;
                } else { // MODE 3
                    float2 res = *(float2*)&Cf[(size_t)rr * N + gcol];
                    int b  = rr >> 14;
                    int n  = (rr >> 6) & 255;
                    int l  = rr & 63;
                    int hh = ((n >> 4) << 3) | (l >> 3);
                    int ww = ((n & 15) << 3) | (l & 7);
                    size_t sbase = ((size_t)(b * 512) << 14) + (size_t)(hh << 7) + ww;
                    out[sbase + ((size_t)gcol << 14)]       = v0 + res.x;
                    out[sbase + ((size_t)(gcol + 1) << 14)] = v1 + res.y;
                }
            }
        }
    }
}

// ---------------------------------------------------------------------------
// Launch sequence
// ---------------------------------------------------------------------------
extern "C" void kernel_launch(void* const* d_in, const int* in_sizes, int n_in,
                              void* d_out, int out_size)
{
    const float* x     = (const float*)d_in[0];
    const float* g1    = (const float*)d_in[1];
    const float* be1   = (const float*)d_in[2];
    const float* g2    = (const float*)d_in[3];
    const float* be2   = (const float*)d_in[4];
    const float* w_qkv = (const float*)d_in[5];
    const float* b_qkv = (const float*)d_in[6];
    const float* w_out = (const float*)d_in[7];
    const float* b_out = (const float*)d_in[8];
    const float* w1    = (const float*)d_in[9];
    const float* b1m   = (const float*)d_in[10];
    const float* w2    = (const float*)d_in[11];
    const float* b2m   = (const float*)d_in[12];
    float* out = (float*)d_out;

    float *t;
    uint32_t *xn, *qkv, *o, *hbuf, *wr;
    cudaGetSymbolAddress((void**)&t,    g_t);
    cudaGetSymbolAddress((void**)&xn,   g_xn);
    cudaGetSymbolAddress((void**)&qkv,  g_qkv);
    cudaGetSymbolAddress((void**)&o,    g_o);
    cudaGetSymbolAddress((void**)&hbuf, g_h);
    cudaGetSymbolAddress((void**)&wr,   g_w);

    cudaFuncSetAttribute(bgemm_k<0>, cudaFuncAttributeMaxDynamicSharedMemorySize, BG_SMEM);
    cudaFuncSetAttribute(bgemm_k<1>, cudaFuncAttributeMaxDynamicSharedMemorySize, BG_SMEM);
    cudaFuncSetAttribute(bgemm_k<2>, cudaFuncAttributeMaxDynamicSharedMemorySize, BG_SMEM);
    cudaFuncSetAttribute(bgemm_k<3>, cudaFuncAttributeMaxDynamicSharedMemorySize, BG_SMEM);

    // 0. pack weights to bf16 k-pair words
    wpack_k<<<WTOT / 256, 256>>>(w_qkv, w_out, w1, w2, wr);
    // 1. window partition + LN1 (coalesced, 8 tokens per CTA)
    ln1_part_k<<<TOKS / 8, 256>>>(x, g1, be1, t, xn);
    // 2. qkv = xn @ w_qkv + b_qkv  (bf16 out)
    bgemm_k<0><<<dim3(12, 1024), 256, BG_SMEM>>>(xn, wr + WQKV_OFF, b_qkv, qkv, nullptr, nullptr, TOKS, 1536, 512);
    // 3. windowed attention (tensor cores)
    attn_k<<<(TOKS / 64) * 8, 128>>>(qkv, o);
    // 4. t += o @ w_out + b_out  (fp32 residual)
    bgemm_k<1><<<dim3(4, 1024), 256, BG_SMEM>>>(o, wr + WOUT_OFF, b_out, nullptr, t, nullptr, TOKS, 512, 512);
    // 5. LN2 (bf16 out)
    ln2_k<<<TOKS, 128>>>(t, g2, be2, xn);
    // 6. h = gelu(xn @ w1 + b1)  (bf16 out)
    bgemm_k<2><<<dim3(16, 1024), 256, BG_SMEM>>>(xn, wr + W1_OFF, b1m, hbuf, nullptr, nullptr, TOKS, 2048, 512);
    // 7. out[x-layout] = t + h @ w2 + b2  (fused un-partition)
    bgemm_k<3><<<dim3(4, 1024), 256, BG_SMEM>>>(hbuf, wr + W2_OFF, b2m, nullptr, t, out, TOKS, 512, 2048);
}